// round 12
// baseline (speedup 1.0000x reference)
#include <cuda_runtime.h>
#include <cuda_fp16.h>
#include <cuda_bf16.h>

#define NN 100000
#define EE 3200000
#define IND 81
#define INDP 84
#define HID 64
#define LAT 32
#define BN_EPS 1e-5f
#define SCAN_BLK 1024

// Scratch (device globals; no allocation allowed)
__device__ __align__(128) __half2 g_half[NN * 32];   // fp16 Hs rows
__device__ float g_bufA[NN * HID];
__device__ float g_bufB[NN * HID];
__device__ float g_dis[NN];
__device__ int   g_cnt[NN];
__device__ int   g_rowptr[NN + 1];
__device__ int   g_rank[EE];
__device__ int   g_csr[EE];
__device__ int   g_bsums[(NN + SCAN_BLK - 1) / SCAN_BLK + 1];
__device__ float g_stats[256];   // [0:128) BN1 raw sums, [128:256) BN2 raw sums

// ---------------------------------------------------------------------------
__device__ __forceinline__ bool edges_are_i64(const void* ei) {
    long long v0 = ((const long long*)ei)[0];
    return (v0 >= 0 && v0 < 1000000LL);
}
__device__ __forceinline__ int edge_at(const void* ei, bool is64, int i) {
    return is64 ? (int)((const long long*)ei)[i] : ((const int*)ei)[i];
}

// ---------------------------------------------------------------------------
// Histogram of dst; the returned old count is the edge's rank within its row.
__global__ void hist_rank(const void* ei, int* __restrict__ cnt,
                          int* __restrict__ rank, int E) {
    int e = blockIdx.x * blockDim.x + threadIdx.x;
    if (e >= E) return;
    bool is64 = edges_are_i64(ei);
    int d = edge_at(ei, is64, E + e);
    rank[e] = atomicAdd(&cnt[d], 1);
}

__global__ void scan1(const int* __restrict__ cnt, int* __restrict__ rowptr,
                      int* __restrict__ bsums, int n) {
    __shared__ int s[SCAN_BLK];
    int t = threadIdx.x;
    int i = blockIdx.x * SCAN_BLK + t;
    int val = (i < n) ? cnt[i] : 0;
    s[t] = val;
    __syncthreads();
    for (int off = 1; off < SCAN_BLK; off <<= 1) {
        int x = (t >= off) ? s[t - off] : 0;
        __syncthreads();
        s[t] += x;
        __syncthreads();
    }
    if (i < n) rowptr[i + 1] = s[t];
    if (t == SCAN_BLK - 1) bsums[blockIdx.x] = s[t];
}

// Add bsums prefix (inline per block), dis = rsqrt(deg+1). No cursor needed.
__global__ void scan3(int* __restrict__ rowptr, const int* __restrict__ bsums,
                      const int* __restrict__ cnt, float* __restrict__ dis,
                      int n, int nb) {
    __shared__ int pre[2];
    int t = threadIdx.x;
    int base = blockIdx.x * 256;
    int jmin = base / SCAN_BLK;
    int jmax = (base + 255) / SCAN_BLK;
    int wid = t >> 5, lane = t & 31;
    if (wid < 2) {
        int j = (wid == 0) ? jmin : jmax;
        int s = 0;
        for (int k = lane; k < j; k += 32) s += bsums[k];
        #pragma unroll
        for (int o = 16; o > 0; o >>= 1) s += __shfl_down_sync(0xffffffffu, s, o);
        if (lane == 0) pre[wid] = s;
    }
    __syncthreads();
    int i = base + t;
    if (i == 0) rowptr[0] = 0;
    if (i < n) {
        int myj = i / SCAN_BLK;
        int off = (myj == jmin) ? pre[0] : pre[1];
        rowptr[i + 1] += off;
        dis[i] = rsqrtf((float)(cnt[i] + 1));
    }
}

// Atomic-free scatter: csr[rowptr[d] + rank[e]] = src.
__global__ void scatter_rank(const void* ei, const int* __restrict__ rowptr,
                             const int* __restrict__ rank, int* __restrict__ csr, int E) {
    int e = blockIdx.x * blockDim.x + threadIdx.x;
    if (e >= E) return;
    bool is64 = edges_are_i64(ei);
    int s = edge_at(ei, is64, e);
    int d = edge_at(ei, is64, E + e);
    csr[__ldg(&rowptr[d]) + __ldg(&rank[e])] = s;
}

// ---------------------------------------------------------------------------
// GEMM: Yh[N,64] = half((X[N,81] @ W[81,64]) * dis[n])
__global__ void gemm81_dis(const float* __restrict__ X, const float* __restrict__ W,
                           const float* __restrict__ dis, __half* __restrict__ Yh, int N) {
    __shared__ float Ws[IND * HID];
    __shared__ __align__(16) float Xs[16][INDP];
    int tx = threadIdx.x;
    int ty = threadIdx.y;
    int tid = ty * 64 + tx;
    for (int i = tid; i < IND * HID; i += 256) Ws[i] = W[i];
    int n0 = blockIdx.x * 16;
    for (int i = tid; i < 16 * IND; i += 256) {
        int r = i / IND, c = i % IND;
        int n = n0 + r;
        Xs[r][c] = (n < N) ? X[n * IND + c] : 0.0f;
    }
    __syncthreads();
    float acc[4] = {0.f, 0.f, 0.f, 0.f};
    #pragma unroll 5
    for (int k = 0; k < 80; k += 4) {
        float w0 = Ws[(k + 0) * HID + tx];
        float w1 = Ws[(k + 1) * HID + tx];
        float w2 = Ws[(k + 2) * HID + tx];
        float w3 = Ws[(k + 3) * HID + tx];
        #pragma unroll
        for (int r = 0; r < 4; ++r) {
            float4 xv = *reinterpret_cast<const float4*>(&Xs[ty * 4 + r][k]);
            acc[r] += xv.x * w0 + xv.y * w1 + xv.z * w2 + xv.w * w3;
        }
    }
    {
        float w = Ws[80 * HID + tx];
        #pragma unroll
        for (int r = 0; r < 4; ++r) acc[r] += Xs[ty * 4 + r][80] * w;
    }
    #pragma unroll
    for (int r = 0; r < 4; ++r) {
        int n = n0 + ty * 4 + r;
        if (n < N) Yh[n * HID + tx] = __float2half(acc[r] * __ldg(&dis[n]));
    }
}

// GEMM with fused BN-finalize + BN-apply + ReLU input transform.
__global__ void gemm64_bn_dis(const float* __restrict__ X, const float* __restrict__ W,
                              const float* __restrict__ rawstats,
                              const float* __restrict__ g, const float* __restrict__ beta,
                              const float* __restrict__ dis,
                              __half* __restrict__ Yh, int N) {
    __shared__ float Ws[HID * HID];
    __shared__ __align__(16) float Xs[16][HID];
    __shared__ float sc[64], sh[64];
    int tx = threadIdx.x;
    int ty = threadIdx.y;
    int tid = ty * 64 + tx;
    for (int i = tid; i < HID * HID; i += 256) Ws[i] = W[i];
    if (tid < 64) {
        float invN = 1.0f / (float)N;
        float m = rawstats[tid] * invN;
        float v = rawstats[64 + tid] * invN - m * m;
        float scale = g[tid] * rsqrtf(v + BN_EPS);
        sc[tid] = scale;
        sh[tid] = beta[tid] - m * scale;
    }
    int n0 = blockIdx.x * 16;
    __syncthreads();
    for (int i = tid; i < 16 * HID; i += 256) {
        int r = i >> 6, c = i & 63;
        int n = n0 + r;
        float raw = (n < N) ? X[n * HID + c] : 0.0f;
        Xs[r][c] = fmaxf(fmaf(raw, sc[c], sh[c]), 0.0f);
    }
    __syncthreads();
    float acc[4] = {0.f, 0.f, 0.f, 0.f};
    #pragma unroll 4
    for (int k = 0; k < HID; k += 4) {
        float w0 = Ws[(k + 0) * HID + tx];
        float w1 = Ws[(k + 1) * HID + tx];
        float w2 = Ws[(k + 2) * HID + tx];
        float w3 = Ws[(k + 3) * HID + tx];
        #pragma unroll
        for (int r = 0; r < 4; ++r) {
            float4 xv = *reinterpret_cast<const float4*>(&Xs[ty * 4 + r][k]);
            acc[r] += xv.x * w0 + xv.y * w1 + xv.z * w2 + xv.w * w3;
        }
    }
    #pragma unroll
    for (int r = 0; r < 4; ++r) {
        int n = n0 + ty * 4 + r;
        if (n < N) Yh[n * HID + tx] = __float2half(acc[r] * __ldg(&dis[n]));
    }
}

// Final heads
__global__ void gemm_mu_ls(const float* __restrict__ X,
                           const float* __restrict__ Wmu, const float* __restrict__ bmu,
                           const float* __restrict__ Wls, const float* __restrict__ bls,
                           float* __restrict__ out, int N) {
    __shared__ float Ws[HID * 64];
    __shared__ float bs[64];
    __shared__ __align__(16) float Xs[16][HID];
    int tx = threadIdx.x;
    int ty = threadIdx.y;
    int tid = ty * 64 + tx;
    for (int i = tid; i < HID * 64; i += 256) {
        int k = i >> 6, f = i & 63;
        Ws[i] = (f < LAT) ? Wmu[k * LAT + f] : Wls[k * LAT + (f - LAT)];
    }
    if (tid < 64) bs[tid] = (tid < LAT) ? bmu[tid] : bls[tid - LAT];
    int n0 = blockIdx.x * 16;
    for (int i = tid; i < 16 * HID; i += 256) {
        int r = i >> 6, c = i & 63;
        int n = n0 + r;
        Xs[r][c] = (n < N) ? X[n * HID + c] : 0.0f;
    }
    __syncthreads();
    float acc[4] = {0.f, 0.f, 0.f, 0.f};
    #pragma unroll 4
    for (int k = 0; k < HID; k += 4) {
        float w0 = Ws[(k + 0) * 64 + tx];
        float w1 = Ws[(k + 1) * 64 + tx];
        float w2 = Ws[(k + 2) * 64 + tx];
        float w3 = Ws[(k + 3) * 64 + tx];
        #pragma unroll
        for (int r = 0; r < 4; ++r) {
            float4 xv = *reinterpret_cast<const float4*>(&Xs[ty * 4 + r][k]);
            acc[r] += xv.x * w0 + xv.y * w1 + xv.z * w2 + xv.w * w3;
        }
    }
    int f = tx & (LAT - 1);
    long long off = (tx < LAT) ? 0 : (long long)N * LAT;
    #pragma unroll
    for (int r = 0; r < 4; ++r) {
        int n = n0 + ty * 4 + r;
        if (n < N) out[off + (long long)n * LAT + f] = acc[r] + bs[tx];
    }
}

// ---------------------------------------------------------------------------
// Aggregation, 2 nodes per warp (unchanged from 387.1us kernel)
__global__ void aggregate_h2(const __half2* __restrict__ Hh, const int* __restrict__ rowptr,
                             const int* __restrict__ csr, const float* __restrict__ dis,
                             const float* __restrict__ bias, float4* __restrict__ out4, int N) {
    int warp = (blockIdx.x * blockDim.x + threadIdx.x) >> 5;
    int lane = threadIdx.x & 31;
    int grp = lane >> 4;
    int sub = lane & 15;
    int n = warp * 2 + grp;
    if (n >= N) return;

    const uint2* Hr = (const uint2*)Hh;
    uint2 raw = __ldg(&Hr[n * 16 + sub]);
    __half2 h0 = *reinterpret_cast<__half2*>(&raw.x);
    __half2 h1 = *reinterpret_cast<__half2*>(&raw.y);
    float2 p0 = __half22float2(h0), p1 = __half22float2(h1);
    float ax0 = p0.x, ay0 = p0.y, az0 = p1.x, aw0 = p1.y;
    float ax1 = 0.f, ay1 = 0.f, az1 = 0.f, aw1 = 0.f;

    int j = __ldg(&rowptr[n]);
    int end = __ldg(&rowptr[n + 1]);
    for (; j + 2 <= end; j += 2) {
        int s0 = __ldg(&csr[j]);
        int s1 = __ldg(&csr[j + 1]);
        uint2 r0 = __ldg(&Hr[s0 * 16 + sub]);
        uint2 r1 = __ldg(&Hr[s1 * 16 + sub]);
        float2 v00 = __half22float2(*reinterpret_cast<__half2*>(&r0.x));
        float2 v01 = __half22float2(*reinterpret_cast<__half2*>(&r0.y));
        float2 v10 = __half22float2(*reinterpret_cast<__half2*>(&r1.x));
        float2 v11 = __half22float2(*reinterpret_cast<__half2*>(&r1.y));
        ax0 += v00.x; ay0 += v00.y; az0 += v01.x; aw0 += v01.y;
        ax1 += v10.x; ay1 += v10.y; az1 += v11.x; aw1 += v11.y;
    }
    if (j < end) {
        int s0 = __ldg(&csr[j]);
        uint2 r0 = __ldg(&Hr[s0 * 16 + sub]);
        float2 v00 = __half22float2(*reinterpret_cast<__half2*>(&r0.x));
        float2 v01 = __half22float2(*reinterpret_cast<__half2*>(&r0.y));
        ax0 += v00.x; ay0 += v00.y; az0 += v01.x; aw0 += v01.y;
    }

    float dd = __ldg(&dis[n]);
    float4 bb = make_float4(0.f, 0.f, 0.f, 0.f);
    if (bias) bb = ((const float4*)bias)[sub];
    out4[n * 16 + sub] = make_float4(fmaf(ax0 + ax1, dd, bb.x),
                                     fmaf(ay0 + ay1, dd, bb.y),
                                     fmaf(az0 + az1, dd, bb.z),
                                     fmaf(aw0 + aw1, dd, bb.w));
}

// ---------------------------------------------------------------------------
// BN stats: raw sum/sumsq accumulated via atomics (buffer pre-zeroed by memset).
__global__ void bn_stats(const float* __restrict__ H, float* stats, int N) {
    int tid = threadIdx.x;
    int col = tid & 63;
    int r = blockIdx.x * 4 + (tid >> 6);
    int rstride = gridDim.x * 4;
    float s = 0.0f, q = 0.0f;
    for (; r < N; r += rstride) {
        float v = H[r * HID + col];
        s += v; q += v * v;
    }
    __shared__ float sh[256], qh[256];
    sh[tid] = s; qh[tid] = q;
    __syncthreads();
    if (tid < 64) {
        float S = sh[tid] + sh[tid + 64] + sh[tid + 128] + sh[tid + 192];
        float Q = qh[tid] + qh[tid + 64] + qh[tid + 128] + qh[tid + 192];
        atomicAdd(&stats[tid], S);
        atomicAdd(&stats[64 + tid], Q);
    }
}

// Hs[n,f] = half(relu(bn(B[n,f])) * dis[n]) — BN finalize in-block from raw sums.
__global__ void bn_relu_dis(const float* __restrict__ H, const float* __restrict__ rawstats,
                            const float* __restrict__ g, const float* __restrict__ beta,
                            const float* __restrict__ dis, __half* __restrict__ out,
                            int total, int N) {
    __shared__ float sc[64], sh[64];
    int t = threadIdx.x;
    if (t < 64) {
        float invN = 1.0f / (float)N;
        float m = rawstats[t] * invN;
        float v = rawstats[64 + t] * invN - m * m;
        float scale = g[t] * rsqrtf(v + BN_EPS);
        sc[t] = scale;
        sh[t] = beta[t] - m * scale;
    }
    __syncthreads();
    int idx = blockIdx.x * blockDim.x + t;
    if (idx >= total) return;
    int f = idx & 63;
    int n = idx >> 6;
    float y = fmaxf(fmaf(H[idx], sc[f], sh[f]), 0.0f);
    out[idx] = __float2half(y * __ldg(&dis[n]));
}

// ---------------------------------------------------------------------------
extern "C" void kernel_launch(void* const* d_in, const int* in_sizes, int n_in,
                              void* d_out, int out_size) {
    const float* x    = (const float*)d_in[0];
    const void*  ei   = d_in[1];
    const float* W1   = (const float*)d_in[2];
    const float* b1   = (const float*)d_in[3];
    const float* g1   = (const float*)d_in[4];
    const float* be1  = (const float*)d_in[5];
    const float* W2   = (const float*)d_in[6];
    const float* b2   = (const float*)d_in[7];
    const float* g2   = (const float*)d_in[8];
    const float* be2  = (const float*)d_in[9];
    const float* Wmu  = (const float*)d_in[10];
    const float* bmu  = (const float*)d_in[11];
    const float* Wls  = (const float*)d_in[12];
    const float* bls  = (const float*)d_in[13];
    float* out = (float*)d_out;

    int N = in_sizes[0] / IND;
    int E = in_sizes[1] / 2;

    float *pA, *pB, *pDis, *pStats;
    __half2* pH;
    int *pCnt, *pRow, *pRank, *pCsr, *pBs;
    cudaGetSymbolAddress((void**)&pA, g_bufA);
    cudaGetSymbolAddress((void**)&pB, g_bufB);
    cudaGetSymbolAddress((void**)&pDis, g_dis);
    cudaGetSymbolAddress((void**)&pStats, g_stats);
    cudaGetSymbolAddress((void**)&pH, g_half);
    cudaGetSymbolAddress((void**)&pCnt, g_cnt);
    cudaGetSymbolAddress((void**)&pRow, g_rowptr);
    cudaGetSymbolAddress((void**)&pRank, g_rank);
    cudaGetSymbolAddress((void**)&pCsr, g_csr);
    cudaGetSymbolAddress((void**)&pBs, g_bsums);

    float* pStats1 = pStats;
    float* pStats2 = pStats + 128;

    int NH = N * HID;
    int nScanBlocks = (N + SCAN_BLK - 1) / SCAN_BLK;
    dim3 gThr(64, 4);
    int gemmGrid = (N + 15) / 16;
    int aggGrid = ((N + 1) / 2 * 32 + 255) / 256;

    // 0. zeroing via memset nodes
    cudaMemsetAsync(pCnt, 0, (size_t)N * sizeof(int));
    cudaMemsetAsync(pStats, 0, 256 * sizeof(float));

    // 1. CSR build: hist (records per-edge rank) -> scan -> atomic-free scatter
    hist_rank<<<(E + 255) / 256, 256>>>(ei, pCnt, pRank, E);
    scan1<<<nScanBlocks, SCAN_BLK>>>(pCnt, pRow, pBs, N);
    scan3<<<(N + 255) / 256, 256>>>(pRow, pBs, pCnt, pDis, N, nScanBlocks);
    scatter_rank<<<(E + 255) / 256, 256>>>(ei, pRow, pRank, pCsr, E);

    // 2. conv1
    gemm81_dis<<<gemmGrid, gThr>>>(x, W1, pDis, (__half*)pH, N);
    aggregate_h2<<<aggGrid, 256>>>(pH, pRow, pCsr, pDis, b1, (float4*)pB, N);

    // 3. BN1 raw stats
    bn_stats<<<512, 256>>>(pB, pStats1, N);

    // 4. conv2
    gemm64_bn_dis<<<gemmGrid, gThr>>>(pB, W2, pStats1, g1, be1, pDis, (__half*)pH, N);
    aggregate_h2<<<aggGrid, 256>>>(pH, pRow, pCsr, pDis, b2, (float4*)pA, N);

    // 5. BN2 raw stats
    bn_stats<<<512, 256>>>(pA, pStats2, N);

    // 6. Hs = relu(bn(A)) * dis ; shared aggregation for both heads
    bn_relu_dis<<<(NH + 255) / 256, 256>>>(pA, pStats2, g2, be2, pDis, (__half*)pH, NH, N);
    aggregate_h2<<<aggGrid, 256>>>(pH, pRow, pCsr, pDis, (const float*)nullptr, (float4*)pB, N);

    // 7. heads
    gemm_mu_ls<<<gemmGrid, gThr>>>(pB, Wmu, bmu, Wls, bls, out, N);
}

// round 13
// speedup vs baseline: 1.0061x; 1.0061x over previous
#include <cuda_runtime.h>
#include <cuda_fp16.h>
#include <cuda_bf16.h>

#define NN 100000
#define EE 3200000
#define IND 81
#define INDP 84
#define HID 64
#define LAT 32
#define BN_EPS 1e-5f
#define SCAN_BLK 1024

// Scratch (device globals; no allocation allowed)
__device__ __align__(128) __half2 g_half[NN * 32];   // fp16 Hs rows
__device__ __align__(128) float g_bufA[NN * HID];    // fp32 agg out / fp16 Z
__device__ __align__(128) float g_bufB[NN * HID];
__device__ float g_dis[NN];
__device__ int   g_cnt[NN];
__device__ int   g_rowptr[NN + 1];
__device__ int   g_cursor[NN + 1];
__device__ int   g_csr[EE];
__device__ int   g_bsums[(NN + SCAN_BLK - 1) / SCAN_BLK + 1];
__device__ float g_stats[256];   // [0:128) BN1 raw sums, [128:256) BN2 raw sums

// ---------------------------------------------------------------------------
__device__ __forceinline__ bool edges_are_i64(const void* ei) {
    long long v0 = ((const long long*)ei)[0];
    return (v0 >= 0 && v0 < 1000000LL);
}
__device__ __forceinline__ int edge_at(const void* ei, bool is64, int i) {
    return is64 ? (int)((const long long*)ei)[i] : ((const int*)ei)[i];
}

// ---------------------------------------------------------------------------
__global__ void hist_dst(const void* ei, int* cnt, int E) {
    int e = blockIdx.x * blockDim.x + threadIdx.x;
    if (e >= E) return;
    bool is64 = edges_are_i64(ei);
    int d = edge_at(ei, is64, E + e);
    atomicAdd(&cnt[d], 1);
}

__global__ void scan1(const int* __restrict__ cnt, int* __restrict__ rowptr,
                      int* __restrict__ bsums, int n) {
    __shared__ int s[SCAN_BLK];
    int t = threadIdx.x;
    int i = blockIdx.x * SCAN_BLK + t;
    int val = (i < n) ? cnt[i] : 0;
    s[t] = val;
    __syncthreads();
    for (int off = 1; off < SCAN_BLK; off <<= 1) {
        int x = (t >= off) ? s[t - off] : 0;
        __syncthreads();
        s[t] += x;
        __syncthreads();
    }
    if (i < n) rowptr[i + 1] = s[t];
    if (t == SCAN_BLK - 1) bsums[blockIdx.x] = s[t];
}

__global__ void scan3(int* __restrict__ rowptr, int* __restrict__ cursor,
                      const int* __restrict__ bsums, const int* __restrict__ cnt,
                      float* __restrict__ dis, int n, int nb) {
    __shared__ int pre[2];
    int t = threadIdx.x;
    int base = blockIdx.x * 256;
    int jmin = base / SCAN_BLK;
    int jmax = (base + 255) / SCAN_BLK;
    int wid = t >> 5, lane = t & 31;
    if (wid < 2) {
        int j = (wid == 0) ? jmin : jmax;
        int s = 0;
        for (int k = lane; k < j; k += 32) s += bsums[k];
        #pragma unroll
        for (int o = 16; o > 0; o >>= 1) s += __shfl_down_sync(0xffffffffu, s, o);
        if (lane == 0) pre[wid] = s;
    }
    __syncthreads();
    int i = base + t;
    if (i == 0) { rowptr[0] = 0; cursor[0] = 0; }
    if (i < n) {
        int myj = i / SCAN_BLK;
        int off = (myj == jmin) ? pre[0] : pre[1];
        int v = rowptr[i + 1] + off;
        rowptr[i + 1] = v;
        cursor[i + 1] = v;
        dis[i] = rsqrtf((float)(cnt[i] + 1));
    }
}

__global__ void scatter_csr(const void* ei, int* __restrict__ cursor,
                            int* __restrict__ csr, int E) {
    int e = blockIdx.x * blockDim.x + threadIdx.x;
    if (e >= E) return;
    bool is64 = edges_are_i64(ei);
    int s = edge_at(ei, is64, e);
    int d = edge_at(ei, is64, E + e);
    int pos = atomicAdd(&cursor[d], 1);
    csr[pos] = s;
}

// ---------------------------------------------------------------------------
// GEMM: Yh[N,64] = half((X[N,81] @ W[81,64]) * dis[n])
__global__ void gemm81_dis(const float* __restrict__ X, const float* __restrict__ W,
                           const float* __restrict__ dis, __half* __restrict__ Yh, int N) {
    __shared__ float Ws[IND * HID];
    __shared__ __align__(16) float Xs[16][INDP];
    int tx = threadIdx.x;
    int ty = threadIdx.y;
    int tid = ty * 64 + tx;
    for (int i = tid; i < IND * HID; i += 256) Ws[i] = W[i];
    int n0 = blockIdx.x * 16;
    for (int i = tid; i < 16 * IND; i += 256) {
        int r = i / IND, c = i % IND;
        int n = n0 + r;
        Xs[r][c] = (n < N) ? X[n * IND + c] : 0.0f;
    }
    __syncthreads();
    float acc[4] = {0.f, 0.f, 0.f, 0.f};
    #pragma unroll 5
    for (int k = 0; k < 80; k += 4) {
        float w0 = Ws[(k + 0) * HID + tx];
        float w1 = Ws[(k + 1) * HID + tx];
        float w2 = Ws[(k + 2) * HID + tx];
        float w3 = Ws[(k + 3) * HID + tx];
        #pragma unroll
        for (int r = 0; r < 4; ++r) {
            float4 xv = *reinterpret_cast<const float4*>(&Xs[ty * 4 + r][k]);
            acc[r] += xv.x * w0 + xv.y * w1 + xv.z * w2 + xv.w * w3;
        }
    }
    {
        float w = Ws[80 * HID + tx];
        #pragma unroll
        for (int r = 0; r < 4; ++r) acc[r] += Xs[ty * 4 + r][80] * w;
    }
    #pragma unroll
    for (int r = 0; r < 4; ++r) {
        int n = n0 + ty * 4 + r;
        if (n < N) Yh[n * HID + tx] = __float2half(acc[r] * __ldg(&dis[n]));
    }
}

// GEMM with fused BN-finalize + BN-apply + ReLU input transform.
__global__ void gemm64_bn_dis(const float* __restrict__ X, const float* __restrict__ W,
                              const float* __restrict__ rawstats,
                              const float* __restrict__ g, const float* __restrict__ beta,
                              const float* __restrict__ dis,
                              __half* __restrict__ Yh, int N) {
    __shared__ float Ws[HID * HID];
    __shared__ __align__(16) float Xs[16][HID];
    __shared__ float sc[64], sh[64];
    int tx = threadIdx.x;
    int ty = threadIdx.y;
    int tid = ty * 64 + tx;
    for (int i = tid; i < HID * HID; i += 256) Ws[i] = W[i];
    if (tid < 64) {
        float invN = 1.0f / (float)N;
        float m = rawstats[tid] * invN;
        float v = rawstats[64 + tid] * invN - m * m;
        float scale = g[tid] * rsqrtf(v + BN_EPS);
        sc[tid] = scale;
        sh[tid] = beta[tid] - m * scale;
    }
    int n0 = blockIdx.x * 16;
    __syncthreads();
    for (int i = tid; i < 16 * HID; i += 256) {
        int r = i >> 6, c = i & 63;
        int n = n0 + r;
        float raw = (n < N) ? X[n * HID + c] : 0.0f;
        Xs[r][c] = fmaxf(fmaf(raw, sc[c], sh[c]), 0.0f);
    }
    __syncthreads();
    float acc[4] = {0.f, 0.f, 0.f, 0.f};
    #pragma unroll 4
    for (int k = 0; k < HID; k += 4) {
        float w0 = Ws[(k + 0) * HID + tx];
        float w1 = Ws[(k + 1) * HID + tx];
        float w2 = Ws[(k + 2) * HID + tx];
        float w3 = Ws[(k + 3) * HID + tx];
        #pragma unroll
        for (int r = 0; r < 4; ++r) {
            float4 xv = *reinterpret_cast<const float4*>(&Xs[ty * 4 + r][k]);
            acc[r] += xv.x * w0 + xv.y * w1 + xv.z * w2 + xv.w * w3;
        }
    }
    #pragma unroll
    for (int r = 0; r < 4; ++r) {
        int n = n0 + ty * 4 + r;
        if (n < N) Yh[n * HID + tx] = __float2half(acc[r] * __ldg(&dis[n]));
    }
}

// Head GEMM before aggregation: Zh[N,64] = half(Hs[N,64] @ [Wmu|Wls])
// (valid because A(Hs)@W == A(Hs@W); bias + dis_n applied in aggregate_out)
__global__ void gemm_z_h(const __half2* __restrict__ Xh,
                         const float* __restrict__ Wmu, const float* __restrict__ Wls,
                         __half* __restrict__ Zh, int N) {
    __shared__ float Ws[HID * 64];
    __shared__ __align__(16) float Xs[16][HID];
    int tx = threadIdx.x;
    int ty = threadIdx.y;
    int tid = ty * 64 + tx;
    for (int i = tid; i < HID * 64; i += 256) {
        int k = i >> 6, f = i & 63;
        Ws[i] = (f < LAT) ? Wmu[k * LAT + f] : Wls[k * LAT + (f - LAT)];
    }
    int n0 = blockIdx.x * 16;
    for (int i = tid; i < 16 * 32; i += 256) {
        int r = i >> 5, c2 = i & 31;
        int n = n0 + r;
        float2 v = (n < N) ? __half22float2(Xh[n * 32 + c2]) : make_float2(0.f, 0.f);
        Xs[r][2 * c2] = v.x;
        Xs[r][2 * c2 + 1] = v.y;
    }
    __syncthreads();
    float acc[4] = {0.f, 0.f, 0.f, 0.f};
    #pragma unroll 4
    for (int k = 0; k < HID; k += 4) {
        float w0 = Ws[(k + 0) * 64 + tx];
        float w1 = Ws[(k + 1) * 64 + tx];
        float w2 = Ws[(k + 2) * 64 + tx];
        float w3 = Ws[(k + 3) * 64 + tx];
        #pragma unroll
        for (int r = 0; r < 4; ++r) {
            float4 xv = *reinterpret_cast<const float4*>(&Xs[ty * 4 + r][k]);
            acc[r] += xv.x * w0 + xv.y * w1 + xv.z * w2 + xv.w * w3;
        }
    }
    #pragma unroll
    for (int r = 0; r < 4; ++r) {
        int n = n0 + ty * 4 + r;
        if (n < N) Zh[n * HID + tx] = __float2half(acc[r]);
    }
}

// ---------------------------------------------------------------------------
// Aggregation, 2 nodes per warp, fp32 output buffer (layers 1-2).
__global__ void aggregate_h2(const __half2* __restrict__ Hh, const int* __restrict__ rowptr,
                             const int* __restrict__ csr, const float* __restrict__ dis,
                             const float* __restrict__ bias, float4* __restrict__ out4, int N) {
    int warp = (blockIdx.x * blockDim.x + threadIdx.x) >> 5;
    int lane = threadIdx.x & 31;
    int grp = lane >> 4;
    int sub = lane & 15;
    int n = warp * 2 + grp;
    if (n >= N) return;

    const uint2* Hr = (const uint2*)Hh;
    uint2 raw = __ldg(&Hr[n * 16 + sub]);
    float2 p0 = __half22float2(*reinterpret_cast<__half2*>(&raw.x));
    float2 p1 = __half22float2(*reinterpret_cast<__half2*>(&raw.y));
    float ax0 = p0.x, ay0 = p0.y, az0 = p1.x, aw0 = p1.y;
    float ax1 = 0.f, ay1 = 0.f, az1 = 0.f, aw1 = 0.f;

    int j = __ldg(&rowptr[n]);
    int end = __ldg(&rowptr[n + 1]);
    for (; j + 2 <= end; j += 2) {
        int s0 = __ldg(&csr[j]);
        int s1 = __ldg(&csr[j + 1]);
        uint2 r0 = __ldg(&Hr[s0 * 16 + sub]);
        uint2 r1 = __ldg(&Hr[s1 * 16 + sub]);
        float2 v00 = __half22float2(*reinterpret_cast<__half2*>(&r0.x));
        float2 v01 = __half22float2(*reinterpret_cast<__half2*>(&r0.y));
        float2 v10 = __half22float2(*reinterpret_cast<__half2*>(&r1.x));
        float2 v11 = __half22float2(*reinterpret_cast<__half2*>(&r1.y));
        ax0 += v00.x; ay0 += v00.y; az0 += v01.x; aw0 += v01.y;
        ax1 += v10.x; ay1 += v10.y; az1 += v11.x; aw1 += v11.y;
    }
    if (j < end) {
        int s0 = __ldg(&csr[j]);
        uint2 r0 = __ldg(&Hr[s0 * 16 + sub]);
        float2 v00 = __half22float2(*reinterpret_cast<__half2*>(&r0.x));
        float2 v01 = __half22float2(*reinterpret_cast<__half2*>(&r0.y));
        ax0 += v00.x; ay0 += v00.y; az0 += v01.x; aw0 += v01.y;
    }

    float dd = __ldg(&dis[n]);
    float4 bb = make_float4(0.f, 0.f, 0.f, 0.f);
    if (bias) bb = ((const float4*)bias)[sub];
    out4[n * 16 + sub] = make_float4(fmaf(ax0 + ax1, dd, bb.x),
                                     fmaf(ay0 + ay1, dd, bb.y),
                                     fmaf(az0 + az1, dd, bb.z),
                                     fmaf(aw0 + aw1, dd, bb.w));
}

// Final aggregation: gathers Z, writes DIRECTLY to out in [mu(N,32); ls(N,32)] layout
// with per-head bias. Lane sub<8 -> mu cols 4sub..4sub+3 ; sub>=8 -> ls cols.
__global__ void aggregate_out(const __half2* __restrict__ Zh, const int* __restrict__ rowptr,
                              const int* __restrict__ csr, const float* __restrict__ dis,
                              const float* __restrict__ bmu, const float* __restrict__ bls,
                              float* __restrict__ out, int N) {
    int warp = (blockIdx.x * blockDim.x + threadIdx.x) >> 5;
    int lane = threadIdx.x & 31;
    int grp = lane >> 4;
    int sub = lane & 15;
    int n = warp * 2 + grp;
    if (n >= N) return;

    const uint2* Hr = (const uint2*)Zh;
    uint2 raw = __ldg(&Hr[n * 16 + sub]);
    float2 p0 = __half22float2(*reinterpret_cast<__half2*>(&raw.x));
    float2 p1 = __half22float2(*reinterpret_cast<__half2*>(&raw.y));
    float ax0 = p0.x, ay0 = p0.y, az0 = p1.x, aw0 = p1.y;
    float ax1 = 0.f, ay1 = 0.f, az1 = 0.f, aw1 = 0.f;

    int j = __ldg(&rowptr[n]);
    int end = __ldg(&rowptr[n + 1]);
    for (; j + 2 <= end; j += 2) {
        int s0 = __ldg(&csr[j]);
        int s1 = __ldg(&csr[j + 1]);
        uint2 r0 = __ldg(&Hr[s0 * 16 + sub]);
        uint2 r1 = __ldg(&Hr[s1 * 16 + sub]);
        float2 v00 = __half22float2(*reinterpret_cast<__half2*>(&r0.x));
        float2 v01 = __half22float2(*reinterpret_cast<__half2*>(&r0.y));
        float2 v10 = __half22float2(*reinterpret_cast<__half2*>(&r1.x));
        float2 v11 = __half22float2(*reinterpret_cast<__half2*>(&r1.y));
        ax0 += v00.x; ay0 += v00.y; az0 += v01.x; aw0 += v01.y;
        ax1 += v10.x; ay1 += v10.y; az1 += v11.x; aw1 += v11.y;
    }
    if (j < end) {
        int s0 = __ldg(&csr[j]);
        uint2 r0 = __ldg(&Hr[s0 * 16 + sub]);
        float2 v00 = __half22float2(*reinterpret_cast<__half2*>(&r0.x));
        float2 v01 = __half22float2(*reinterpret_cast<__half2*>(&r0.y));
        ax0 += v00.x; ay0 += v00.y; az0 += v01.x; aw0 += v01.y;
    }

    float dd = __ldg(&dis[n]);
    bool isMu = (sub < 8);
    float4 bb = isMu ? ((const float4*)bmu)[sub] : ((const float4*)bls)[sub - 8];
    long long headOff = isMu ? 0 : (long long)N * LAT;
    int col = (4 * sub) & (LAT - 1);
    float4* dst = reinterpret_cast<float4*>(out + headOff + (long long)n * LAT + col);
    *dst = make_float4(fmaf(ax0 + ax1, dd, bb.x),
                       fmaf(ay0 + ay1, dd, bb.y),
                       fmaf(az0 + az1, dd, bb.z),
                       fmaf(aw0 + aw1, dd, bb.w));
}

// ---------------------------------------------------------------------------
// BN stats: raw sum/sumsq accumulated via atomics (buffer pre-zeroed by memset).
__global__ void bn_stats(const float* __restrict__ H, float* stats, int N) {
    int tid = threadIdx.x;
    int col = tid & 63;
    int r = blockIdx.x * 4 + (tid >> 6);
    int rstride = gridDim.x * 4;
    float s = 0.0f, q = 0.0f;
    for (; r < N; r += rstride) {
        float v = H[r * HID + col];
        s += v; q += v * v;
    }
    __shared__ float sh[256], qh[256];
    sh[tid] = s; qh[tid] = q;
    __syncthreads();
    if (tid < 64) {
        float S = sh[tid] + sh[tid + 64] + sh[tid + 128] + sh[tid + 192];
        float Q = qh[tid] + qh[tid + 64] + qh[tid + 128] + qh[tid + 192];
        atomicAdd(&stats[tid], S);
        atomicAdd(&stats[64 + tid], Q);
    }
}

// Hs[n,f] = half(relu(bn(B[n,f])) * dis[n]) — BN finalize in-block from raw sums.
__global__ void bn_relu_dis(const float* __restrict__ H, const float* __restrict__ rawstats,
                            const float* __restrict__ g, const float* __restrict__ beta,
                            const float* __restrict__ dis, __half* __restrict__ out,
                            int total, int N) {
    __shared__ float sc[64], sh[64];
    int t = threadIdx.x;
    if (t < 64) {
        float invN = 1.0f / (float)N;
        float m = rawstats[t] * invN;
        float v = rawstats[64 + t] * invN - m * m;
        float scale = g[t] * rsqrtf(v + BN_EPS);
        sc[t] = scale;
        sh[t] = beta[t] - m * scale;
    }
    __syncthreads();
    int idx = blockIdx.x * blockDim.x + t;
    if (idx >= total) return;
    int f = idx & 63;
    int n = idx >> 6;
    float y = fmaxf(fmaf(H[idx], sc[f], sh[f]), 0.0f);
    out[idx] = __float2half(y * __ldg(&dis[n]));
}

// ---------------------------------------------------------------------------
extern "C" void kernel_launch(void* const* d_in, const int* in_sizes, int n_in,
                              void* d_out, int out_size) {
    const float* x    = (const float*)d_in[0];
    const void*  ei   = d_in[1];
    const float* W1   = (const float*)d_in[2];
    const float* b1   = (const float*)d_in[3];
    const float* g1   = (const float*)d_in[4];
    const float* be1  = (const float*)d_in[5];
    const float* W2   = (const float*)d_in[6];
    const float* b2   = (const float*)d_in[7];
    const float* g2   = (const float*)d_in[8];
    const float* be2  = (const float*)d_in[9];
    const float* Wmu  = (const float*)d_in[10];
    const float* bmu  = (const float*)d_in[11];
    const float* Wls  = (const float*)d_in[12];
    const float* bls  = (const float*)d_in[13];
    float* out = (float*)d_out;

    int N = in_sizes[0] / IND;
    int E = in_sizes[1] / 2;

    float *pA, *pB, *pDis, *pStats;
    __half2* pH;
    int *pCnt, *pRow, *pCur, *pCsr, *pBs;
    cudaGetSymbolAddress((void**)&pA, g_bufA);
    cudaGetSymbolAddress((void**)&pB, g_bufB);
    cudaGetSymbolAddress((void**)&pDis, g_dis);
    cudaGetSymbolAddress((void**)&pStats, g_stats);
    cudaGetSymbolAddress((void**)&pH, g_half);
    cudaGetSymbolAddress((void**)&pCnt, g_cnt);
    cudaGetSymbolAddress((void**)&pRow, g_rowptr);
    cudaGetSymbolAddress((void**)&pCur, g_cursor);
    cudaGetSymbolAddress((void**)&pCsr, g_csr);
    cudaGetSymbolAddress((void**)&pBs, g_bsums);

    float* pStats1 = pStats;
    float* pStats2 = pStats + 128;

    int NH = N * HID;
    int nScanBlocks = (N + SCAN_BLK - 1) / SCAN_BLK;
    dim3 gThr(64, 4);
    int gemmGrid = (N + 15) / 16;
    int aggGrid = ((N + 1) / 2 * 32 + 255) / 256;

    // 0. zeroing via memset nodes
    cudaMemsetAsync(pCnt, 0, (size_t)N * sizeof(int));
    cudaMemsetAsync(pStats, 0, 256 * sizeof(float));

    // 1. CSR build + normalization (round-9 form)
    hist_dst<<<(E + 255) / 256, 256>>>(ei, pCnt, E);
    scan1<<<nScanBlocks, SCAN_BLK>>>(pCnt, pRow, pBs, N);
    scan3<<<(N + 255) / 256, 256>>>(pRow, pCur, pBs, pCnt, pDis, N, nScanBlocks);
    scatter_csr<<<(E + 255) / 256, 256>>>(ei, pCur, pCsr, E);

    // 2. conv1
    gemm81_dis<<<gemmGrid, gThr>>>(x, W1, pDis, (__half*)pH, N);
    aggregate_h2<<<aggGrid, 256>>>(pH, pRow, pCsr, pDis, b1, (float4*)pB, N);

    // 3. BN1 raw stats (finalize fused into gemm64)
    bn_stats<<<512, 256>>>(pB, pStats1, N);

    // 4. conv2
    gemm64_bn_dis<<<gemmGrid, gThr>>>(pB, W2, pStats1, g1, be1, pDis, (__half*)pH, N);
    aggregate_h2<<<aggGrid, 256>>>(pH, pRow, pCsr, pDis, b2, (float4*)pA, N);

    // 5. BN2 raw stats (finalize fused into bn_relu_dis)
    bn_stats<<<512, 256>>>(pA, pStats2, N);

    // 6. Hs = relu(bn(A)) * dis ; head GEMM commuted BEFORE the final aggregate
    bn_relu_dis<<<(NH + 255) / 256, 256>>>(pA, pStats2, g2, be2, pDis, (__half*)pH, NH, N);
    gemm_z_h<<<gemmGrid, gThr>>>(pH, Wmu, Wls, (__half*)pB, N);

    // 7. final aggregate writes out directly (dis + bias in epilogue)
    aggregate_out<<<aggGrid, 256>>>((const __half2*)pB, pRow, pCsr, pDis, bmu, bls, out, N);
}

// round 14
// speedup vs baseline: 1.0121x; 1.0060x over previous
#include <cuda_runtime.h>
#include <cuda_fp16.h>
#include <cuda_bf16.h>

#define NN 100000
#define EE 3200000
#define IND 81
#define INDP 84
#define HID 64
#define LAT 32
#define BN_EPS 1e-5f
#define SCAN_BLK 1024

// Scratch (device globals; no allocation allowed)
__device__ __align__(128) __half2 g_half[NN * 32];   // fp16 Hs rows
__device__ float g_bufA[NN * HID];
__device__ float g_bufB[NN * HID];
__device__ float g_dis[NN];
__device__ int   g_cnt[NN];
__device__ int   g_rowptr[NN + 1];
__device__ int   g_cursor[NN + 1];
__device__ int   g_csr[EE];
__device__ int   g_bsums[(NN + SCAN_BLK - 1) / SCAN_BLK + 1];
__device__ float g_stats[256];   // [0:128) BN1 raw sums, [128:256) BN2 raw sums

// ---------------------------------------------------------------------------
__device__ __forceinline__ bool edges_are_i64(const void* ei) {
    long long v0 = ((const long long*)ei)[0];
    return (v0 >= 0 && v0 < 1000000LL);
}
__device__ __forceinline__ int edge_at(const void* ei, bool is64, int i) {
    return is64 ? (int)((const long long*)ei)[i] : ((const int*)ei)[i];
}

// ---------------------------------------------------------------------------
__global__ void hist_dst(const void* ei, int* cnt, int E) {
    int e = blockIdx.x * blockDim.x + threadIdx.x;
    if (e >= E) return;
    bool is64 = edges_are_i64(ei);
    int d = edge_at(ei, is64, E + e);
    atomicAdd(&cnt[d], 1);
}

__global__ void scan1(const int* __restrict__ cnt, int* __restrict__ rowptr,
                      int* __restrict__ bsums, int n) {
    __shared__ int s[SCAN_BLK];
    int t = threadIdx.x;
    int i = blockIdx.x * SCAN_BLK + t;
    int val = (i < n) ? cnt[i] : 0;
    s[t] = val;
    __syncthreads();
    for (int off = 1; off < SCAN_BLK; off <<= 1) {
        int x = (t >= off) ? s[t - off] : 0;
        __syncthreads();
        s[t] += x;
        __syncthreads();
    }
    if (i < n) rowptr[i + 1] = s[t];
    if (t == SCAN_BLK - 1) bsums[blockIdx.x] = s[t];
}

__global__ void scan3(int* __restrict__ rowptr, int* __restrict__ cursor,
                      const int* __restrict__ bsums, const int* __restrict__ cnt,
                      float* __restrict__ dis, int n, int nb) {
    __shared__ int pre[2];
    int t = threadIdx.x;
    int base = blockIdx.x * 256;
    int jmin = base / SCAN_BLK;
    int jmax = (base + 255) / SCAN_BLK;
    int wid = t >> 5, lane = t & 31;
    if (wid < 2) {
        int j = (wid == 0) ? jmin : jmax;
        int s = 0;
        for (int k = lane; k < j; k += 32) s += bsums[k];
        #pragma unroll
        for (int o = 16; o > 0; o >>= 1) s += __shfl_down_sync(0xffffffffu, s, o);
        if (lane == 0) pre[wid] = s;
    }
    __syncthreads();
    int i = base + t;
    if (i == 0) { rowptr[0] = 0; cursor[0] = 0; }
    if (i < n) {
        int myj = i / SCAN_BLK;
        int off = (myj == jmin) ? pre[0] : pre[1];
        int v = rowptr[i + 1] + off;
        rowptr[i + 1] = v;
        cursor[i + 1] = v;
        dis[i] = rsqrtf((float)(cnt[i] + 1));
    }
}

// ---------------------------------------------------------------------------
// FUSED: blocks [0, scatGrid) do the CSR scatter (L2/latency-bound);
// blocks [scatGrid, scatGrid+gemmGrid) do conv1's GEMM (FMA/LDS-bound).
// One launch => guaranteed co-residency; the GEMM soaks up the issue slots the
// scatter leaves idle (measured issue=6% on scatter standalone).
__global__ void scatter_gemm81(const void* ei, int* __restrict__ cursor,
                               int* __restrict__ csr, int E,
                               const float* __restrict__ X, const float* __restrict__ W,
                               const float* __restrict__ dis, __half* __restrict__ Yh,
                               int N, int scatGrid) {
    if (blockIdx.x < scatGrid) {
        // ---- scatter body ----
        int e = blockIdx.x * blockDim.x + threadIdx.x;
        if (e >= E) return;
        bool is64 = edges_are_i64(ei);
        int s = edge_at(ei, is64, e);
        int d = edge_at(ei, is64, E + e);
        int pos = atomicAdd(&cursor[d], 1);
        csr[pos] = s;
    } else {
        // ---- gemm81 body ----
        __shared__ float Ws[IND * HID];
        __shared__ __align__(16) float Xs[16][INDP];
        int tid = threadIdx.x;          // 256 threads flat
        int tx = tid & 63;
        int ty = tid >> 6;
        for (int i = tid; i < IND * HID; i += 256) Ws[i] = W[i];
        int n0 = (blockIdx.x - scatGrid) * 16;
        for (int i = tid; i < 16 * IND; i += 256) {
            int r = i / IND, c = i % IND;
            int n = n0 + r;
            Xs[r][c] = (n < N) ? X[n * IND + c] : 0.0f;
        }
        __syncthreads();
        float acc[4] = {0.f, 0.f, 0.f, 0.f};
        #pragma unroll 5
        for (int k = 0; k < 80; k += 4) {
            float w0 = Ws[(k + 0) * HID + tx];
            float w1 = Ws[(k + 1) * HID + tx];
            float w2 = Ws[(k + 2) * HID + tx];
            float w3 = Ws[(k + 3) * HID + tx];
            #pragma unroll
            for (int r = 0; r < 4; ++r) {
                float4 xv = *reinterpret_cast<const float4*>(&Xs[ty * 4 + r][k]);
                acc[r] += xv.x * w0 + xv.y * w1 + xv.z * w2 + xv.w * w3;
            }
        }
        {
            float w = Ws[80 * HID + tx];
            #pragma unroll
            for (int r = 0; r < 4; ++r) acc[r] += Xs[ty * 4 + r][80] * w;
        }
        #pragma unroll
        for (int r = 0; r < 4; ++r) {
            int n = n0 + ty * 4 + r;
            if (n < N) Yh[n * HID + tx] = __float2half(acc[r] * __ldg(&dis[n]));
        }
    }
}

// ---------------------------------------------------------------------------
// GEMM with fused BN-finalize + BN-apply + ReLU input transform.
__global__ void gemm64_bn_dis(const float* __restrict__ X, const float* __restrict__ W,
                              const float* __restrict__ rawstats,
                              const float* __restrict__ g, const float* __restrict__ beta,
                              const float* __restrict__ dis,
                              __half* __restrict__ Yh, int N) {
    __shared__ float Ws[HID * HID];
    __shared__ __align__(16) float Xs[16][HID];
    __shared__ float sc[64], sh[64];
    int tx = threadIdx.x;
    int ty = threadIdx.y;
    int tid = ty * 64 + tx;
    for (int i = tid; i < HID * HID; i += 256) Ws[i] = W[i];
    if (tid < 64) {
        float invN = 1.0f / (float)N;
        float m = rawstats[tid] * invN;
        float v = rawstats[64 + tid] * invN - m * m;
        float scale = g[tid] * rsqrtf(v + BN_EPS);
        sc[tid] = scale;
        sh[tid] = beta[tid] - m * scale;
    }
    int n0 = blockIdx.x * 16;
    __syncthreads();
    for (int i = tid; i < 16 * HID; i += 256) {
        int r = i >> 6, c = i & 63;
        int n = n0 + r;
        float raw = (n < N) ? X[n * HID + c] : 0.0f;
        Xs[r][c] = fmaxf(fmaf(raw, sc[c], sh[c]), 0.0f);
    }
    __syncthreads();
    float acc[4] = {0.f, 0.f, 0.f, 0.f};
    #pragma unroll 4
    for (int k = 0; k < HID; k += 4) {
        float w0 = Ws[(k + 0) * HID + tx];
        float w1 = Ws[(k + 1) * HID + tx];
        float w2 = Ws[(k + 2) * HID + tx];
        float w3 = Ws[(k + 3) * HID + tx];
        #pragma unroll
        for (int r = 0; r < 4; ++r) {
            float4 xv = *reinterpret_cast<const float4*>(&Xs[ty * 4 + r][k]);
            acc[r] += xv.x * w0 + xv.y * w1 + xv.z * w2 + xv.w * w3;
        }
    }
    #pragma unroll
    for (int r = 0; r < 4; ++r) {
        int n = n0 + ty * 4 + r;
        if (n < N) Yh[n * HID + tx] = __float2half(acc[r] * __ldg(&dis[n]));
    }
}

// Final heads
__global__ void gemm_mu_ls(const float* __restrict__ X,
                           const float* __restrict__ Wmu, const float* __restrict__ bmu,
                           const float* __restrict__ Wls, const float* __restrict__ bls,
                           float* __restrict__ out, int N) {
    __shared__ float Ws[HID * 64];
    __shared__ float bs[64];
    __shared__ __align__(16) float Xs[16][HID];
    int tx = threadIdx.x;
    int ty = threadIdx.y;
    int tid = ty * 64 + tx;
    for (int i = tid; i < HID * 64; i += 256) {
        int k = i >> 6, f = i & 63;
        Ws[i] = (f < LAT) ? Wmu[k * LAT + f] : Wls[k * LAT + (f - LAT)];
    }
    if (tid < 64) bs[tid] = (tid < LAT) ? bmu[tid] : bls[tid - LAT];
    int n0 = blockIdx.x * 16;
    for (int i = tid; i < 16 * HID; i += 256) {
        int r = i >> 6, c = i & 63;
        int n = n0 + r;
        Xs[r][c] = (n < N) ? X[n * HID + c] : 0.0f;
    }
    __syncthreads();
    float acc[4] = {0.f, 0.f, 0.f, 0.f};
    #pragma unroll 4
    for (int k = 0; k < HID; k += 4) {
        float w0 = Ws[(k + 0) * 64 + tx];
        float w1 = Ws[(k + 1) * 64 + tx];
        float w2 = Ws[(k + 2) * 64 + tx];
        float w3 = Ws[(k + 3) * 64 + tx];
        #pragma unroll
        for (int r = 0; r < 4; ++r) {
            float4 xv = *reinterpret_cast<const float4*>(&Xs[ty * 4 + r][k]);
            acc[r] += xv.x * w0 + xv.y * w1 + xv.z * w2 + xv.w * w3;
        }
    }
    int f = tx & (LAT - 1);
    long long off = (tx < LAT) ? 0 : (long long)N * LAT;
    #pragma unroll
    for (int r = 0; r < 4; ++r) {
        int n = n0 + ty * 4 + r;
        if (n < N) out[off + (long long)n * LAT + f] = acc[r] + bs[tx];
    }
}

// ---------------------------------------------------------------------------
// Aggregation, 2 nodes per warp (unchanged from 387.1us kernel)
__global__ void aggregate_h2(const __half2* __restrict__ Hh, const int* __restrict__ rowptr,
                             const int* __restrict__ csr, const float* __restrict__ dis,
                             const float* __restrict__ bias, float4* __restrict__ out4, int N) {
    int warp = (blockIdx.x * blockDim.x + threadIdx.x) >> 5;
    int lane = threadIdx.x & 31;
    int grp = lane >> 4;
    int sub = lane & 15;
    int n = warp * 2 + grp;
    if (n >= N) return;

    const uint2* Hr = (const uint2*)Hh;
    uint2 raw = __ldg(&Hr[n * 16 + sub]);
    __half2 h0 = *reinterpret_cast<__half2*>(&raw.x);
    __half2 h1 = *reinterpret_cast<__half2*>(&raw.y);
    float2 p0 = __half22float2(h0), p1 = __half22float2(h1);
    float ax0 = p0.x, ay0 = p0.y, az0 = p1.x, aw0 = p1.y;
    float ax1 = 0.f, ay1 = 0.f, az1 = 0.f, aw1 = 0.f;

    int j = __ldg(&rowptr[n]);
    int end = __ldg(&rowptr[n + 1]);
    for (; j + 2 <= end; j += 2) {
        int s0 = __ldg(&csr[j]);
        int s1 = __ldg(&csr[j + 1]);
        uint2 r0 = __ldg(&Hr[s0 * 16 + sub]);
        uint2 r1 = __ldg(&Hr[s1 * 16 + sub]);
        float2 v00 = __half22float2(*reinterpret_cast<__half2*>(&r0.x));
        float2 v01 = __half22float2(*reinterpret_cast<__half2*>(&r0.y));
        float2 v10 = __half22float2(*reinterpret_cast<__half2*>(&r1.x));
        float2 v11 = __half22float2(*reinterpret_cast<__half2*>(&r1.y));
        ax0 += v00.x; ay0 += v00.y; az0 += v01.x; aw0 += v01.y;
        ax1 += v10.x; ay1 += v10.y; az1 += v11.x; aw1 += v11.y;
    }
    if (j < end) {
        int s0 = __ldg(&csr[j]);
        uint2 r0 = __ldg(&Hr[s0 * 16 + sub]);
        float2 v00 = __half22float2(*reinterpret_cast<__half2*>(&r0.x));
        float2 v01 = __half22float2(*reinterpret_cast<__half2*>(&r0.y));
        ax0 += v00.x; ay0 += v00.y; az0 += v01.x; aw0 += v01.y;
    }

    float dd = __ldg(&dis[n]);
    float4 bb = make_float4(0.f, 0.f, 0.f, 0.f);
    if (bias) bb = ((const float4*)bias)[sub];
    out4[n * 16 + sub] = make_float4(fmaf(ax0 + ax1, dd, bb.x),
                                     fmaf(ay0 + ay1, dd, bb.y),
                                     fmaf(az0 + az1, dd, bb.z),
                                     fmaf(aw0 + aw1, dd, bb.w));
}

// ---------------------------------------------------------------------------
// BN stats: raw sum/sumsq accumulated via atomics (buffer pre-zeroed by memset).
__global__ void bn_stats(const float* __restrict__ H, float* stats, int N) {
    int tid = threadIdx.x;
    int col = tid & 63;
    int r = blockIdx.x * 4 + (tid >> 6);
    int rstride = gridDim.x * 4;
    float s = 0.0f, q = 0.0f;
    for (; r < N; r += rstride) {
        float v = H[r * HID + col];
        s += v; q += v * v;
    }
    __shared__ float sh[256], qh[256];
    sh[tid] = s; qh[tid] = q;
    __syncthreads();
    if (tid < 64) {
        float S = sh[tid] + sh[tid + 64] + sh[tid + 128] + sh[tid + 192];
        float Q = qh[tid] + qh[tid + 64] + qh[tid + 128] + qh[tid + 192];
        atomicAdd(&stats[tid], S);
        atomicAdd(&stats[64 + tid], Q);
    }
}

// Hs[n,f] = half(relu(bn(B[n,f])) * dis[n]) — BN finalize in-block from raw sums.
__global__ void bn_relu_dis(const float* __restrict__ H, const float* __restrict__ rawstats,
                            const float* __restrict__ g, const float* __restrict__ beta,
                            const float* __restrict__ dis, __half* __restrict__ out,
                            int total, int N) {
    __shared__ float sc[64], sh[64];
    int t = threadIdx.x;
    if (t < 64) {
        float invN = 1.0f / (float)N;
        float m = rawstats[t] * invN;
        float v = rawstats[64 + t] * invN - m * m;
        float scale = g[t] * rsqrtf(v + BN_EPS);
        sc[t] = scale;
        sh[t] = beta[t] - m * scale;
    }
    __syncthreads();
    int idx = blockIdx.x * blockDim.x + t;
    if (idx >= total) return;
    int f = idx & 63;
    int n = idx >> 6;
    float y = fmaxf(fmaf(H[idx], sc[f], sh[f]), 0.0f);
    out[idx] = __float2half(y * __ldg(&dis[n]));
}

// ---------------------------------------------------------------------------
extern "C" void kernel_launch(void* const* d_in, const int* in_sizes, int n_in,
                              void* d_out, int out_size) {
    const float* x    = (const float*)d_in[0];
    const void*  ei   = d_in[1];
    const float* W1   = (const float*)d_in[2];
    const float* b1   = (const float*)d_in[3];
    const float* g1   = (const float*)d_in[4];
    const float* be1  = (const float*)d_in[5];
    const float* W2   = (const float*)d_in[6];
    const float* b2   = (const float*)d_in[7];
    const float* g2   = (const float*)d_in[8];
    const float* be2  = (const float*)d_in[9];
    const float* Wmu  = (const float*)d_in[10];
    const float* bmu  = (const float*)d_in[11];
    const float* Wls  = (const float*)d_in[12];
    const float* bls  = (const float*)d_in[13];
    float* out = (float*)d_out;

    int N = in_sizes[0] / IND;
    int E = in_sizes[1] / 2;

    float *pA, *pB, *pDis, *pStats;
    __half2* pH;
    int *pCnt, *pRow, *pCur, *pCsr, *pBs;
    cudaGetSymbolAddress((void**)&pA, g_bufA);
    cudaGetSymbolAddress((void**)&pB, g_bufB);
    cudaGetSymbolAddress((void**)&pDis, g_dis);
    cudaGetSymbolAddress((void**)&pStats, g_stats);
    cudaGetSymbolAddress((void**)&pH, g_half);
    cudaGetSymbolAddress((void**)&pCnt, g_cnt);
    cudaGetSymbolAddress((void**)&pRow, g_rowptr);
    cudaGetSymbolAddress((void**)&pCur, g_cursor);
    cudaGetSymbolAddress((void**)&pCsr, g_csr);
    cudaGetSymbolAddress((void**)&pBs, g_bsums);

    float* pStats1 = pStats;
    float* pStats2 = pStats + 128;

    int NH = N * HID;
    int nScanBlocks = (N + SCAN_BLK - 1) / SCAN_BLK;
    dim3 gThr(64, 4);
    int gemmGrid = (N + 15) / 16;
    int aggGrid = ((N + 1) / 2 * 32 + 255) / 256;
    int scatGrid = (E + 255) / 256;

    // 0. zeroing via memset nodes
    cudaMemsetAsync(pCnt, 0, (size_t)N * sizeof(int));
    cudaMemsetAsync(pStats, 0, 256 * sizeof(float));

    // 1. CSR build start
    hist_dst<<<(E + 255) / 256, 256>>>(ei, pCnt, E);
    scan1<<<nScanBlocks, SCAN_BLK>>>(pCnt, pRow, pBs, N);
    scan3<<<(N + 255) / 256, 256>>>(pRow, pCur, pBs, pCnt, pDis, N, nScanBlocks);

    // 2. FUSED scatter + conv1 GEMM (co-resident heterogeneous blocks)
    scatter_gemm81<<<scatGrid + gemmGrid, 256>>>(ei, pCur, pCsr, E,
                                                 x, W1, pDis, (__half*)pH, N, scatGrid);

    // 3. conv1 aggregate
    aggregate_h2<<<aggGrid, 256>>>(pH, pRow, pCsr, pDis, b1, (float4*)pB, N);

    // 4. BN1 raw stats (finalize fused into gemm64)
    bn_stats<<<512, 256>>>(pB, pStats1, N);

    // 5. conv2
    gemm64_bn_dis<<<gemmGrid, gThr>>>(pB, W2, pStats1, g1, be1, pDis, (__half*)pH, N);
    aggregate_h2<<<aggGrid, 256>>>(pH, pRow, pCsr, pDis, b2, (float4*)pA, N);

    // 6. BN2 raw stats (finalize fused into bn_relu_dis)
    bn_stats<<<512, 256>>>(pA, pStats2, N);

    // 7. Hs = relu(bn(A)) * dis ; shared aggregation for both heads
    bn_relu_dis<<<(NH + 255) / 256, 256>>>(pA, pStats2, g2, be2, pDis, (__half*)pH, NH, N);
    aggregate_h2<<<aggGrid, 256>>>(pH, pRow, pCsr, pDis, (const float*)nullptr, (float4*)pB, N);

    // 8. heads
    gemm_mu_ls<<<gemmGrid, gThr>>>(pB, Wmu, bmu, Wls, bls, out, N);
}

// round 15
// speedup vs baseline: 1.0122x; 1.0002x over previous
#include <cuda_runtime.h>
#include <cuda_fp16.h>
#include <cuda_bf16.h>

#define NN 100000
#define EE 3200000
#define IND 81
#define INDP 84
#define HID 64
#define LAT 32
#define BN_EPS 1e-5f
#define SCAN_BLK 1024

// Scratch (device globals; no allocation allowed)
__device__ __align__(128) __half2 g_half[NN * 32];   // fp16 Hs rows
__device__ float g_bufA[NN * HID];
__device__ float g_bufB[NN * HID];
__device__ float g_dis[NN];
__device__ int   g_cnt[NN];
__device__ int   g_rowptr[NN + 1];
__device__ int   g_cursor[NN + 1];
__device__ int   g_csr[EE];
__device__ int   g_bsums[(NN + SCAN_BLK - 1) / SCAN_BLK + 1];
__device__ float g_stats[256];   // [0:128) BN1 raw sums, [128:256) BN2 raw sums

// ---------------------------------------------------------------------------
__device__ __forceinline__ bool edges_are_i64(const void* ei) {
    long long v0 = ((const long long*)ei)[0];
    return (v0 >= 0 && v0 < 1000000LL);
}
__device__ __forceinline__ int edge_at(const void* ei, bool is64, int i) {
    return is64 ? (int)((const long long*)ei)[i] : ((const int*)ei)[i];
}

// ---------------------------------------------------------------------------
__global__ void hist_dst(const void* ei, int* cnt, int E) {
    int e = blockIdx.x * blockDim.x + threadIdx.x;
    if (e >= E) return;
    bool is64 = edges_are_i64(ei);
    int d = edge_at(ei, is64, E + e);
    atomicAdd(&cnt[d], 1);
}

__global__ void scan1(const int* __restrict__ cnt, int* __restrict__ rowptr,
                      int* __restrict__ bsums, int n) {
    __shared__ int s[SCAN_BLK];
    int t = threadIdx.x;
    int i = blockIdx.x * SCAN_BLK + t;
    int val = (i < n) ? cnt[i] : 0;
    s[t] = val;
    __syncthreads();
    for (int off = 1; off < SCAN_BLK; off <<= 1) {
        int x = (t >= off) ? s[t - off] : 0;
        __syncthreads();
        s[t] += x;
        __syncthreads();
    }
    if (i < n) rowptr[i + 1] = s[t];
    if (t == SCAN_BLK - 1) bsums[blockIdx.x] = s[t];
}

__global__ void scan3(int* __restrict__ rowptr, int* __restrict__ cursor,
                      const int* __restrict__ bsums, const int* __restrict__ cnt,
                      float* __restrict__ dis, int n, int nb) {
    __shared__ int pre[2];
    int t = threadIdx.x;
    int base = blockIdx.x * 256;
    int jmin = base / SCAN_BLK;
    int jmax = (base + 255) / SCAN_BLK;
    int wid = t >> 5, lane = t & 31;
    if (wid < 2) {
        int j = (wid == 0) ? jmin : jmax;
        int s = 0;
        for (int k = lane; k < j; k += 32) s += bsums[k];
        #pragma unroll
        for (int o = 16; o > 0; o >>= 1) s += __shfl_down_sync(0xffffffffu, s, o);
        if (lane == 0) pre[wid] = s;
    }
    __syncthreads();
    int i = base + t;
    if (i == 0) { rowptr[0] = 0; cursor[0] = 0; }
    if (i < n) {
        int myj = i / SCAN_BLK;
        int off = (myj == jmin) ? pre[0] : pre[1];
        int v = rowptr[i + 1] + off;
        rowptr[i + 1] = v;
        cursor[i + 1] = v;
        dis[i] = rsqrtf((float)(cnt[i] + 1));
    }
}

// ---------------------------------------------------------------------------
// FUSED scatter + conv1 GEMM with INTERLEAVED block roles (2 scatter : 1 gemm),
// so every scheduling wave co-hosts latency-bound scatter blocks and
// compute-bound gemm blocks on the same SMs.
__global__ void __launch_bounds__(256, 8)
scatter_gemm81(const void* ei, int* __restrict__ cursor,
               int* __restrict__ csr, int E,
               const float* __restrict__ X, const float* __restrict__ W,
               const float* __restrict__ dis, __half* __restrict__ Yh,
               int N, int scatGrid, int gemmGrid) {
    int bid = blockIdx.x;
    int trip = bid / 3;
    int rem = bid - trip * 3;
    // roles: rem 0,1 -> scatter block (idx = trip*2+rem); rem 2 -> gemm block (idx = trip)
    // tail blocks beyond 3*min(...) handled by range checks below.
    int scatIdx, gemmIdx;
    bool isScat;
    if (rem < 2) { isScat = true;  scatIdx = trip * 2 + rem; }
    else         { isScat = false; gemmIdx = trip; }
    // If interleaving overruns one side (grids not exactly 2:1), remap overflow.
    if (isScat && scatIdx >= scatGrid) { isScat = false; gemmIdx = gemmGrid - 1 - (scatIdx - scatGrid); }
    if (!isScat && gemmIdx >= gemmGrid) { isScat = true; scatIdx = scatGrid - 1 - (gemmIdx - gemmGrid); }

    if (isScat) {
        if (scatIdx < 0 || scatIdx >= scatGrid) return;
        int e = scatIdx * 256 + threadIdx.x;
        if (e >= E) return;
        bool is64 = edges_are_i64(ei);
        int s = edge_at(ei, is64, e);
        int d = edge_at(ei, is64, E + e);
        int pos = atomicAdd(&cursor[d], 1);
        csr[pos] = s;
    } else {
        if (gemmIdx < 0 || gemmIdx >= gemmGrid) return;
        __shared__ float Ws[IND * HID];
        __shared__ __align__(16) float Xs[16][INDP];
        int tid = threadIdx.x;
        int tx = tid & 63;
        int ty = tid >> 6;
        for (int i = tid; i < IND * HID; i += 256) Ws[i] = W[i];
        int n0 = gemmIdx * 16;
        for (int i = tid; i < 16 * IND; i += 256) {
            int r = i / IND, c = i % IND;
            int n = n0 + r;
            Xs[r][c] = (n < N) ? X[n * IND + c] : 0.0f;
        }
        __syncthreads();
        float acc[4] = {0.f, 0.f, 0.f, 0.f};
        #pragma unroll 5
        for (int k = 0; k < 80; k += 4) {
            float w0 = Ws[(k + 0) * HID + tx];
            float w1 = Ws[(k + 1) * HID + tx];
            float w2 = Ws[(k + 2) * HID + tx];
            float w3 = Ws[(k + 3) * HID + tx];
            #pragma unroll
            for (int r = 0; r < 4; ++r) {
                float4 xv = *reinterpret_cast<const float4*>(&Xs[ty * 4 + r][k]);
                acc[r] += xv.x * w0 + xv.y * w1 + xv.z * w2 + xv.w * w3;
            }
        }
        {
            float w = Ws[80 * HID + tx];
            #pragma unroll
            for (int r = 0; r < 4; ++r) acc[r] += Xs[ty * 4 + r][80] * w;
        }
        #pragma unroll
        for (int r = 0; r < 4; ++r) {
            int n = n0 + ty * 4 + r;
            if (n < N) Yh[n * HID + tx] = __float2half(acc[r] * __ldg(&dis[n]));
        }
    }
}

// ---------------------------------------------------------------------------
// GEMM with fused BN-finalize + BN-apply + ReLU input transform.
__global__ void gemm64_bn_dis(const float* __restrict__ X, const float* __restrict__ W,
                              const float* __restrict__ rawstats,
                              const float* __restrict__ g, const float* __restrict__ beta,
                              const float* __restrict__ dis,
                              __half* __restrict__ Yh, int N) {
    __shared__ float Ws[HID * HID];
    __shared__ __align__(16) float Xs[16][HID];
    __shared__ float sc[64], sh[64];
    int tx = threadIdx.x;
    int ty = threadIdx.y;
    int tid = ty * 64 + tx;
    for (int i = tid; i < HID * HID; i += 256) Ws[i] = W[i];
    if (tid < 64) {
        float invN = 1.0f / (float)N;
        float m = rawstats[tid] * invN;
        float v = rawstats[64 + tid] * invN - m * m;
        float scale = g[tid] * rsqrtf(v + BN_EPS);
        sc[tid] = scale;
        sh[tid] = beta[tid] - m * scale;
    }
    int n0 = blockIdx.x * 16;
    __syncthreads();
    for (int i = tid; i < 16 * HID; i += 256) {
        int r = i >> 6, c = i & 63;
        int n = n0 + r;
        float raw = (n < N) ? X[n * HID + c] : 0.0f;
        Xs[r][c] = fmaxf(fmaf(raw, sc[c], sh[c]), 0.0f);
    }
    __syncthreads();
    float acc[4] = {0.f, 0.f, 0.f, 0.f};
    #pragma unroll 4
    for (int k = 0; k < HID; k += 4) {
        float w0 = Ws[(k + 0) * HID + tx];
        float w1 = Ws[(k + 1) * HID + tx];
        float w2 = Ws[(k + 2) * HID + tx];
        float w3 = Ws[(k + 3) * HID + tx];
        #pragma unroll
        for (int r = 0; r < 4; ++r) {
            float4 xv = *reinterpret_cast<const float4*>(&Xs[ty * 4 + r][k]);
            acc[r] += xv.x * w0 + xv.y * w1 + xv.z * w2 + xv.w * w3;
        }
    }
    #pragma unroll
    for (int r = 0; r < 4; ++r) {
        int n = n0 + ty * 4 + r;
        if (n < N) Yh[n * HID + tx] = __float2half(acc[r] * __ldg(&dis[n]));
    }
}

// Final heads
__global__ void gemm_mu_ls(const float* __restrict__ X,
                           const float* __restrict__ Wmu, const float* __restrict__ bmu,
                           const float* __restrict__ Wls, const float* __restrict__ bls,
                           float* __restrict__ out, int N) {
    __shared__ float Ws[HID * 64];
    __shared__ float bs[64];
    __shared__ __align__(16) float Xs[16][HID];
    int tx = threadIdx.x;
    int ty = threadIdx.y;
    int tid = ty * 64 + tx;
    for (int i = tid; i < HID * 64; i += 256) {
        int k = i >> 6, f = i & 63;
        Ws[i] = (f < LAT) ? Wmu[k * LAT + f] : Wls[k * LAT + (f - LAT)];
    }
    if (tid < 64) bs[tid] = (tid < LAT) ? bmu[tid] : bls[tid - LAT];
    int n0 = blockIdx.x * 16;
    for (int i = tid; i < 16 * HID; i += 256) {
        int r = i >> 6, c = i & 63;
        int n = n0 + r;
        Xs[r][c] = (n < N) ? X[n * HID + c] : 0.0f;
    }
    __syncthreads();
    float acc[4] = {0.f, 0.f, 0.f, 0.f};
    #pragma unroll 4
    for (int k = 0; k < HID; k += 4) {
        float w0 = Ws[(k + 0) * 64 + tx];
        float w1 = Ws[(k + 1) * 64 + tx];
        float w2 = Ws[(k + 2) * 64 + tx];
        float w3 = Ws[(k + 3) * 64 + tx];
        #pragma unroll
        for (int r = 0; r < 4; ++r) {
            float4 xv = *reinterpret_cast<const float4*>(&Xs[ty * 4 + r][k]);
            acc[r] += xv.x * w0 + xv.y * w1 + xv.z * w2 + xv.w * w3;
        }
    }
    int f = tx & (LAT - 1);
    long long off = (tx < LAT) ? 0 : (long long)N * LAT;
    #pragma unroll
    for (int r = 0; r < 4; ++r) {
        int n = n0 + ty * 4 + r;
        if (n < N) out[off + (long long)n * LAT + f] = acc[r] + bs[tx];
    }
}

// ---------------------------------------------------------------------------
// Aggregation, 2 nodes per warp (unchanged)
__global__ void aggregate_h2(const __half2* __restrict__ Hh, const int* __restrict__ rowptr,
                             const int* __restrict__ csr, const float* __restrict__ dis,
                             const float* __restrict__ bias, float4* __restrict__ out4, int N) {
    int warp = (blockIdx.x * blockDim.x + threadIdx.x) >> 5;
    int lane = threadIdx.x & 31;
    int grp = lane >> 4;
    int sub = lane & 15;
    int n = warp * 2 + grp;
    if (n >= N) return;

    const uint2* Hr = (const uint2*)Hh;
    uint2 raw = __ldg(&Hr[n * 16 + sub]);
    __half2 h0 = *reinterpret_cast<__half2*>(&raw.x);
    __half2 h1 = *reinterpret_cast<__half2*>(&raw.y);
    float2 p0 = __half22float2(h0), p1 = __half22float2(h1);
    float ax0 = p0.x, ay0 = p0.y, az0 = p1.x, aw0 = p1.y;
    float ax1 = 0.f, ay1 = 0.f, az1 = 0.f, aw1 = 0.f;

    int j = __ldg(&rowptr[n]);
    int end = __ldg(&rowptr[n + 1]);
    for (; j + 2 <= end; j += 2) {
        int s0 = __ldg(&csr[j]);
        int s1 = __ldg(&csr[j + 1]);
        uint2 r0 = __ldg(&Hr[s0 * 16 + sub]);
        uint2 r1 = __ldg(&Hr[s1 * 16 + sub]);
        float2 v00 = __half22float2(*reinterpret_cast<__half2*>(&r0.x));
        float2 v01 = __half22float2(*reinterpret_cast<__half2*>(&r0.y));
        float2 v10 = __half22float2(*reinterpret_cast<__half2*>(&r1.x));
        float2 v11 = __half22float2(*reinterpret_cast<__half2*>(&r1.y));
        ax0 += v00.x; ay0 += v00.y; az0 += v01.x; aw0 += v01.y;
        ax1 += v10.x; ay1 += v10.y; az1 += v11.x; aw1 += v11.y;
    }
    if (j < end) {
        int s0 = __ldg(&csr[j]);
        uint2 r0 = __ldg(&Hr[s0 * 16 + sub]);
        float2 v00 = __half22float2(*reinterpret_cast<__half2*>(&r0.x));
        float2 v01 = __half22float2(*reinterpret_cast<__half2*>(&r0.y));
        ax0 += v00.x; ay0 += v00.y; az0 += v01.x; aw0 += v01.y;
    }

    float dd = __ldg(&dis[n]);
    float4 bb = make_float4(0.f, 0.f, 0.f, 0.f);
    if (bias) bb = ((const float4*)bias)[sub];
    out4[n * 16 + sub] = make_float4(fmaf(ax0 + ax1, dd, bb.x),
                                     fmaf(ay0 + ay1, dd, bb.y),
                                     fmaf(az0 + az1, dd, bb.z),
                                     fmaf(aw0 + aw1, dd, bb.w));
}

// ---------------------------------------------------------------------------
// BN stats: raw sum/sumsq accumulated via atomics (buffer pre-zeroed by memset).
__global__ void bn_stats(const float* __restrict__ H, float* stats, int N) {
    int tid = threadIdx.x;
    int col = tid & 63;
    int r = blockIdx.x * 4 + (tid >> 6);
    int rstride = gridDim.x * 4;
    float s = 0.0f, q = 0.0f;
    for (; r < N; r += rstride) {
        float v = H[r * HID + col];
        s += v; q += v * v;
    }
    __shared__ float sh[256], qh[256];
    sh[tid] = s; qh[tid] = q;
    __syncthreads();
    if (tid < 64) {
        float S = sh[tid] + sh[tid + 64] + sh[tid + 128] + sh[tid + 192];
        float Q = qh[tid] + qh[tid + 64] + qh[tid + 128] + qh[tid + 192];
        atomicAdd(&stats[tid], S);
        atomicAdd(&stats[64 + tid], Q);
    }
}

// Hs[n,f] = half(relu(bn(B[n,f])) * dis[n]) — BN finalize in-block from raw sums.
__global__ void bn_relu_dis(const float* __restrict__ H, const float* __restrict__ rawstats,
                            const float* __restrict__ g, const float* __restrict__ beta,
                            const float* __restrict__ dis, __half* __restrict__ out,
                            int total, int N) {
    __shared__ float sc[64], sh[64];
    int t = threadIdx.x;
    if (t < 64) {
        float invN = 1.0f / (float)N;
        float m = rawstats[t] * invN;
        float v = rawstats[64 + t] * invN - m * m;
        float scale = g[t] * rsqrtf(v + BN_EPS);
        sc[t] = scale;
        sh[t] = beta[t] - m * scale;
    }
    __syncthreads();
    int idx = blockIdx.x * blockDim.x + t;
    if (idx >= total) return;
    int f = idx & 63;
    int n = idx >> 6;
    float y = fmaxf(fmaf(H[idx], sc[f], sh[f]), 0.0f);
    out[idx] = __float2half(y * __ldg(&dis[n]));
}

// ---------------------------------------------------------------------------
extern "C" void kernel_launch(void* const* d_in, const int* in_sizes, int n_in,
                              void* d_out, int out_size) {
    const float* x    = (const float*)d_in[0];
    const void*  ei   = d_in[1];
    const float* W1   = (const float*)d_in[2];
    const float* b1   = (const float*)d_in[3];
    const float* g1   = (const float*)d_in[4];
    const float* be1  = (const float*)d_in[5];
    const float* W2   = (const float*)d_in[6];
    const float* b2   = (const float*)d_in[7];
    const float* g2   = (const float*)d_in[8];
    const float* be2  = (const float*)d_in[9];
    const float* Wmu  = (const float*)d_in[10];
    const float* bmu  = (const float*)d_in[11];
    const float* Wls  = (const float*)d_in[12];
    const float* bls  = (const float*)d_in[13];
    float* out = (float*)d_out;

    int N = in_sizes[0] / IND;
    int E = in_sizes[1] / 2;

    float *pA, *pB, *pDis, *pStats;
    __half2* pH;
    int *pCnt, *pRow, *pCur, *pCsr, *pBs;
    cudaGetSymbolAddress((void**)&pA, g_bufA);
    cudaGetSymbolAddress((void**)&pB, g_bufB);
    cudaGetSymbolAddress((void**)&pDis, g_dis);
    cudaGetSymbolAddress((void**)&pStats, g_stats);
    cudaGetSymbolAddress((void**)&pH, g_half);
    cudaGetSymbolAddress((void**)&pCnt, g_cnt);
    cudaGetSymbolAddress((void**)&pRow, g_rowptr);
    cudaGetSymbolAddress((void**)&pCur, g_cursor);
    cudaGetSymbolAddress((void**)&pCsr, g_csr);
    cudaGetSymbolAddress((void**)&pBs, g_bsums);

    float* pStats1 = pStats;
    float* pStats2 = pStats + 128;

    int NH = N * HID;
    int nScanBlocks = (N + SCAN_BLK - 1) / SCAN_BLK;
    dim3 gThr(64, 4);
    int gemmGrid = (N + 15) / 16;
    int aggGrid = ((N + 1) / 2 * 32 + 255) / 256;
    int scatGrid = (E + 255) / 256;

    // 0. zeroing via memset nodes
    cudaMemsetAsync(pCnt, 0, (size_t)N * sizeof(int));
    cudaMemsetAsync(pStats, 0, 256 * sizeof(float));

    // 1. CSR build start
    hist_dst<<<(E + 255) / 256, 256>>>(ei, pCnt, E);
    scan1<<<nScanBlocks, SCAN_BLK>>>(pCnt, pRow, pBs, N);
    scan3<<<(N + 255) / 256, 256>>>(pRow, pCur, pBs, pCnt, pDis, N, nScanBlocks);

    // 2. FUSED scatter + conv1 GEMM, roles interleaved 2:1 per wave
    scatter_gemm81<<<scatGrid + gemmGrid, 256>>>(ei, pCur, pCsr, E,
                                                 x, W1, pDis, (__half*)pH, N,
                                                 scatGrid, gemmGrid);

    // 3. conv1 aggregate
    aggregate_h2<<<aggGrid, 256>>>(pH, pRow, pCsr, pDis, b1, (float4*)pB, N);

    // 4. BN1 raw stats (finalize fused into gemm64)
    bn_stats<<<512, 256>>>(pB, pStats1, N);

    // 5. conv2
    gemm64_bn_dis<<<gemmGrid, gThr>>>(pB, W2, pStats1, g1, be1, pDis, (__half*)pH, N);
    aggregate_h2<<<aggGrid, 256>>>(pH, pRow, pCsr, pDis, b2, (float4*)pA, N);

    // 6. BN2 raw stats (finalize fused into bn_relu_dis)
    bn_stats<<<512, 256>>>(pA, pStats2, N);

    // 7. Hs = relu(bn(A)) * dis ; shared aggregation for both heads
    bn_relu_dis<<<(NH + 255) / 256, 256>>>(pA, pStats2, g2, be2, pDis, (__half*)pH, NH, N);
    aggregate_h2<<<aggGrid, 256>>>(pH, pRow, pCsr, pDis, (const float*)nullptr, (float4*)pB, N);

    // 8. heads
    gemm_mu_ls<<<gemmGrid, gThr>>>(pB, Wmu, bmu, Wls, bls, out, N);
}

// round 16
// speedup vs baseline: 1.2517x; 1.2365x over previous
#include <cuda_runtime.h>
#include <cuda_fp16.h>
#include <cuda_bf16.h>

#define NN 100000
#define EE 3200000
#define IND 81
#define HID 64
#define LAT 32
#define BN_EPS 1e-5f
#define SCAN_BLK 1024
#define XP81 92
#define WP81 92
#define XP64 68

__device__ __align__(128) __half2 g_half[NN * 32];
__device__ float g_bufA[NN * HID];
__device__ float g_bufB[NN * HID];
__device__ float g_dis[NN];
__device__ int   g_cnt[NN];
__device__ int   g_rowptr[NN + 1];
__device__ int   g_cursor[NN + 1];
__device__ int   g_csr[EE];
__device__ int   g_bsums[(NN + SCAN_BLK - 1) / SCAN_BLK + 1];
__device__ float g_stats[256];

// ---------------------------------------------------------------------------
__device__ __forceinline__ bool edges_are_i64(const void* ei) {
    long long v0 = ((const long long*)ei)[0];
    return (v0 >= 0 && v0 < 1000000LL);
}
__device__ __forceinline__ int edge_at(const void* ei, bool is64, int i) {
    return is64 ? (int)((const long long*)ei)[i] : ((const int*)ei)[i];
}
__device__ __forceinline__ unsigned f2tf(float f) {
    unsigned r;
    asm("cvt.rna.tf32.f32 %0, %1;" : "=r"(r) : "f"(f));
    return r;
}
__device__ __forceinline__ void mma_tf32(float* c, unsigned a0, unsigned a1,
                                         unsigned a2, unsigned a3,
                                         unsigned b0, unsigned b1) {
    asm("mma.sync.aligned.m16n8k8.row.col.f32.tf32.tf32.f32 "
        "{%0,%1,%2,%3},{%4,%5,%6,%7},{%8,%9},{%0,%1,%2,%3};"
        : "+f"(c[0]), "+f"(c[1]), "+f"(c[2]), "+f"(c[3])
        : "r"(a0), "r"(a1), "r"(a2), "r"(a3), "r"(b0), "r"(b1));
}

// ---------------------------------------------------------------------------
__global__ void hist_dst(const void* ei, int* cnt, int E) {
    int e = blockIdx.x * blockDim.x + threadIdx.x;
    if (e >= E) return;
    bool is64 = edges_are_i64(ei);
    int d = edge_at(ei, is64, E + e);
    atomicAdd(&cnt[d], 1);
}

__global__ void scan1(const int* __restrict__ cnt, int* __restrict__ rowptr,
                      int* __restrict__ bsums, int n) {
    __shared__ int s[SCAN_BLK];
    int t = threadIdx.x;
    int i = blockIdx.x * SCAN_BLK + t;
    int val = (i < n) ? cnt[i] : 0;
    s[t] = val;
    __syncthreads();
    for (int off = 1; off < SCAN_BLK; off <<= 1) {
        int x = (t >= off) ? s[t - off] : 0;
        __syncthreads();
        s[t] += x;
        __syncthreads();
    }
    if (i < n) rowptr[i + 1] = s[t];
    if (t == SCAN_BLK - 1) bsums[blockIdx.x] = s[t];
}

__global__ void scan3(int* __restrict__ rowptr, int* __restrict__ cursor,
                      const int* __restrict__ bsums, const int* __restrict__ cnt,
                      float* __restrict__ dis, int n, int nb) {
    __shared__ int pre[2];
    int t = threadIdx.x;
    int base = blockIdx.x * 256;
    int jmin = base / SCAN_BLK;
    int jmax = (base + 255) / SCAN_BLK;
    int wid = t >> 5, lane = t & 31;
    if (wid < 2) {
        int j = (wid == 0) ? jmin : jmax;
        int s = 0;
        for (int k = lane; k < j; k += 32) s += bsums[k];
        #pragma unroll
        for (int o = 16; o > 0; o >>= 1) s += __shfl_down_sync(0xffffffffu, s, o);
        if (lane == 0) pre[wid] = s;
    }
    __syncthreads();
    int i = base + t;
    if (i == 0) { rowptr[0] = 0; cursor[0] = 0; }
    if (i < n) {
        int myj = i / SCAN_BLK;
        int off = (myj == jmin) ? pre[0] : pre[1];
        int v = rowptr[i + 1] + off;
        rowptr[i + 1] = v;
        cursor[i + 1] = v;
        dis[i] = rsqrtf((float)(cnt[i] + 1));
    }
}

__global__ void scatter_csr(const void* ei, int* __restrict__ cursor,
                            int* __restrict__ csr, int E) {
    int e = blockIdx.x * blockDim.x + threadIdx.x;
    if (e >= E) return;
    bool is64 = edges_are_i64(ei);
    int s = edge_at(ei, is64, e);
    int d = edge_at(ei, is64, E + e);
    int pos = atomicAdd(&cursor[d], 1);
    csr[pos] = s;
}

// ---------------------------------------------------------------------------
// tf32 tensor-core GEMM: Yh[N,64] = half((X[N,81] @ W[81,64]) * dis[n])
__global__ void gemm81_mma(const float* __restrict__ X, const float* __restrict__ W,
                           const float* __restrict__ dis, __half2* __restrict__ Yh2, int N) {
    __shared__ float Xs[64 * XP81];
    __shared__ float Wt[64 * WP81];
    int tid = threadIdx.x;
    int n0 = blockIdx.x * 64;

    for (int i = tid; i < 64 * XP81; i += 256) Xs[i] = 0.0f;
    for (int i = tid; i < 64 * WP81; i += 256) Wt[i] = 0.0f;
    __syncthreads();
    for (int i = tid; i < 64 * IND; i += 256) {
        int r = i / IND, c = i % IND;
        int n = n0 + r;
        if (n < N) Xs[r * XP81 + c] = X[n * IND + c];
    }
    for (int i = tid; i < IND * HID; i += 256) {
        int k = i >> 6, n = i & 63;
        Wt[n * WP81 + k] = W[i];
    }
    __syncthreads();

    int warp = tid >> 5, lane = tid & 31;
    int mt = warp & 3, nh = warp >> 2;
    int qr = lane >> 2, qc = lane & 3;
    int rowA = mt * 16 + qr;

    float c[4][4];
    #pragma unroll
    for (int t = 0; t < 4; ++t) { c[t][0] = c[t][1] = c[t][2] = c[t][3] = 0.f; }

    for (int k0 = 0; k0 <= 80; k0 += 8) {
        unsigned a0 = f2tf(Xs[rowA * XP81 + k0 + qc]);
        unsigned a1 = f2tf(Xs[(rowA + 8) * XP81 + k0 + qc]);
        unsigned a2 = f2tf(Xs[rowA * XP81 + k0 + 4 + qc]);
        unsigned a3 = f2tf(Xs[(rowA + 8) * XP81 + k0 + 4 + qc]);
        #pragma unroll
        for (int nt = 0; nt < 4; ++nt) {
            int nc = nh * 32 + nt * 8 + qr;
            unsigned b0 = f2tf(Wt[nc * WP81 + k0 + qc]);
            unsigned b1 = f2tf(Wt[nc * WP81 + k0 + 4 + qc]);
            mma_tf32(c[nt], a0, a1, a2, a3, b0, b1);
        }
    }

    int r0 = n0 + mt * 16 + qr;
    int r1 = r0 + 8;
    float d0 = (r0 < N) ? __ldg(&dis[r0]) : 0.f;
    float d1 = (r1 < N) ? __ldg(&dis[r1]) : 0.f;
    #pragma unroll
    for (int nt = 0; nt < 4; ++nt) {
        int cb = nh * 32 + nt * 8 + 2 * qc;
        if (r0 < N) Yh2[r0 * 32 + (cb >> 1)] = __floats2half2_rn(c[nt][0] * d0, c[nt][1] * d0);
        if (r1 < N) Yh2[r1 * 32 + (cb >> 1)] = __floats2half2_rn(c[nt][2] * d1, c[nt][3] * d1);
    }
}

// tf32 GEMM with fused BN-finalize + BN-apply + ReLU; X is fp32 (aggregate output).
__global__ void gemm64_bn_mma(const float* __restrict__ X, const float* __restrict__ W,
                              const float* __restrict__ rawstats,
                              const float* __restrict__ g, const float* __restrict__ beta,
                              const float* __restrict__ dis,
                              __half2* __restrict__ Yh2, int N) {
    __shared__ float Xs[64 * XP64];
    __shared__ float Wt[64 * XP64];
    __shared__ float sc[64], sh[64];
    int tid = threadIdx.x;
    int n0 = blockIdx.x * 64;

    if (tid < 64) {
        float invN = 1.0f / (float)N;
        float m = rawstats[tid] * invN;
        float v = rawstats[64 + tid] * invN - m * m;
        float scale = g[tid] * rsqrtf(v + BN_EPS);
        sc[tid] = scale;
        sh[tid] = beta[tid] - m * scale;
    }
    __syncthreads();
    for (int i = tid; i < 64 * HID; i += 256) {
        int r = i >> 6, cc = i & 63;
        int n = n0 + r;
        float raw = (n < N) ? X[n * HID + cc] : 0.0f;
        Xs[r * XP64 + cc] = fmaxf(fmaf(raw, sc[cc], sh[cc]), 0.0f);
    }
    for (int i = tid; i < HID * HID; i += 256) {
        int k = i >> 6, n = i & 63;
        Wt[n * XP64 + k] = W[i];
    }
    __syncthreads();

    int warp = tid >> 5, lane = tid & 31;
    int mt = warp & 3, nh = warp >> 2;
    int qr = lane >> 2, qc = lane & 3;
    int rowA = mt * 16 + qr;

    float c[4][4];
    #pragma unroll
    for (int t = 0; t < 4; ++t) { c[t][0] = c[t][1] = c[t][2] = c[t][3] = 0.f; }

    for (int k0 = 0; k0 < 64; k0 += 8) {
        unsigned a0 = f2tf(Xs[rowA * XP64 + k0 + qc]);
        unsigned a1 = f2tf(Xs[(rowA + 8) * XP64 + k0 + qc]);
        unsigned a2 = f2tf(Xs[rowA * XP64 + k0 + 4 + qc]);
        unsigned a3 = f2tf(Xs[(rowA + 8) * XP64 + k0 + 4 + qc]);
        #pragma unroll
        for (int nt = 0; nt < 4; ++nt) {
            int nc = nh * 32 + nt * 8 + qr;
            unsigned b0 = f2tf(Wt[nc * XP64 + k0 + qc]);
            unsigned b1 = f2tf(Wt[nc * XP64 + k0 + 4 + qc]);
            mma_tf32(c[nt], a0, a1, a2, a3, b0, b1);
        }
    }

    int r0 = n0 + mt * 16 + qr;
    int r1 = r0 + 8;
    float d0 = (r0 < N) ? __ldg(&dis[r0]) : 0.f;
    float d1 = (r1 < N) ? __ldg(&dis[r1]) : 0.f;
    #pragma unroll
    for (int nt = 0; nt < 4; ++nt) {
        int cb = nh * 32 + nt * 8 + 2 * qc;
        if (r0 < N) Yh2[r0 * 32 + (cb >> 1)] = __floats2half2_rn(c[nt][0] * d0, c[nt][1] * d0);
        if (r1 < N) Yh2[r1 * 32 + (cb >> 1)] = __floats2half2_rn(c[nt][2] * d1, c[nt][3] * d1);
    }
}

// tf32 GEMM for heads: out = [X@Wmu + bmu ; X@Wls + bls], X fp32.
__global__ void gemm_mu_ls_mma(const float* __restrict__ X,
                               const float* __restrict__ Wmu, const float* __restrict__ bmu,
                               const float* __restrict__ Wls, const float* __restrict__ bls,
                               float* __restrict__ out, int N) {
    __shared__ float Xs[64 * XP64];
    __shared__ float Wt[64 * XP64];
    __shared__ float bs[64];
    int tid = threadIdx.x;
    int n0 = blockIdx.x * 64;

    if (tid < 64) bs[tid] = (tid < LAT) ? bmu[tid] : bls[tid - LAT];
    for (int i = tid; i < 64 * HID; i += 256) {
        int r = i >> 6, cc = i & 63;
        int n = n0 + r;
        Xs[r * XP64 + cc] = (n < N) ? X[n * HID + cc] : 0.0f;
    }
    for (int i = tid; i < HID * 64; i += 256) {
        int k = i >> 6, n = i & 63;
        Wt[n * XP64 + k] = (n < LAT) ? Wmu[k * LAT + n] : Wls[k * LAT + (n - LAT)];
    }
    __syncthreads();

    int warp = tid >> 5, lane = tid & 31;
    int mt = warp & 3, nh = warp >> 2;
    int qr = lane >> 2, qc = lane & 3;
    int rowA = mt * 16 + qr;

    float c[4][4];
    #pragma unroll
    for (int t = 0; t < 4; ++t) { c[t][0] = c[t][1] = c[t][2] = c[t][3] = 0.f; }

    for (int k0 = 0; k0 < 64; k0 += 8) {
        unsigned a0 = f2tf(Xs[rowA * XP64 + k0 + qc]);
        unsigned a1 = f2tf(Xs[(rowA + 8) * XP64 + k0 + qc]);
        unsigned a2 = f2tf(Xs[rowA * XP64 + k0 + 4 + qc]);
        unsigned a3 = f2tf(Xs[(rowA + 8) * XP64 + k0 + 4 + qc]);
        #pragma unroll
        for (int nt = 0; nt < 4; ++nt) {
            int nc = nh * 32 + nt * 8 + qr;
            unsigned b0 = f2tf(Wt[nc * XP64 + k0 + qc]);
            unsigned b1 = f2tf(Wt[nc * XP64 + k0 + 4 + qc]);
            mma_tf32(c[nt], a0, a1, a2, a3, b0, b1);
        }
    }

    int r0 = n0 + mt * 16 + qr;
    int r1 = r0 + 8;
    long long headOff = nh ? (long long)N * LAT : 0;
    #pragma unroll
    for (int nt = 0; nt < 4; ++nt) {
        int cb = nh * 32 + nt * 8 + 2 * qc;
        int col = cb & (LAT - 1);
        float bx = bs[cb], by = bs[cb + 1];
        if (r0 < N) {
            float2* p = reinterpret_cast<float2*>(out + headOff + (long long)r0 * LAT + col);
            *p = make_float2(c[nt][0] + bx, c[nt][1] + by);
        }
        if (r1 < N) {
            float2* p = reinterpret_cast<float2*>(out + headOff + (long long)r1 * LAT + col);
            *p = make_float2(c[nt][2] + bx, c[nt][3] + by);
        }
    }
}

// ---------------------------------------------------------------------------
__global__ void aggregate_h2(const __half2* __restrict__ Hh, const int* __restrict__ rowptr,
                             const int* __restrict__ csr, const float* __restrict__ dis,
                             const float* __restrict__ bias, float4* __restrict__ out4, int N) {
    int warp = (blockIdx.x * blockDim.x + threadIdx.x) >> 5;
    int lane = threadIdx.x & 31;
    int grp = lane >> 4;
    int sub = lane & 15;
    int n = warp * 2 + grp;
    if (n >= N) return;

    const uint2* Hr = (const uint2*)Hh;
    uint2 raw = __ldg(&Hr[n * 16 + sub]);
    float2 p0 = __half22float2(*reinterpret_cast<__half2*>(&raw.x));
    float2 p1 = __half22float2(*reinterpret_cast<__half2*>(&raw.y));
    float ax0 = p0.x, ay0 = p0.y, az0 = p1.x, aw0 = p1.y;
    float ax1 = 0.f, ay1 = 0.f, az1 = 0.f, aw1 = 0.f;

    int j = __ldg(&rowptr[n]);
    int end = __ldg(&rowptr[n + 1]);
    for (; j + 2 <= end; j += 2) {
        int s0 = __ldg(&csr[j]);
        int s1 = __ldg(&csr[j + 1]);
        uint2 r0 = __ldg(&Hr[s0 * 16 + sub]);
        uint2 r1 = __ldg(&Hr[s1 * 16 + sub]);
        float2 v00 = __half22float2(*reinterpret_cast<__half2*>(&r0.x));
        float2 v01 = __half22float2(*reinterpret_cast<__half2*>(&r0.y));
        float2 v10 = __half22float2(*reinterpret_cast<__half2*>(&r1.x));
        float2 v11 = __half22float2(*reinterpret_cast<__half2*>(&r1.y));
        ax0 += v00.x; ay0 += v00.y; az0 += v01.x; aw0 += v01.y;
        ax1 += v10.x; ay1 += v10.y; az1 += v11.x; aw1 += v11.y;
    }
    if (j < end) {
        int s0 = __ldg(&csr[j]);
        uint2 r0 = __ldg(&Hr[s0 * 16 + sub]);
        float2 v00 = __half22float2(*reinterpret_cast<__half2*>(&r0.x));
        float2 v01 = __half22float2(*reinterpret_cast<__half2*>(&r0.y));
        ax0 += v00.x; ay0 += v00.y; az0 += v01.x; aw0 += v01.y;
    }

    float dd = __ldg(&dis[n]);
    float4 bb = make_float4(0.f, 0.f, 0.f, 0.f);
    if (bias) bb = ((const float4*)bias)[sub];
    out4[n * 16 + sub] = make_float4(fmaf(ax0 + ax1, dd, bb.x),
                                     fmaf(ay0 + ay1, dd, bb.y),
                                     fmaf(az0 + az1, dd, bb.z),
                                     fmaf(aw0 + aw1, dd, bb.w));
}

// ---------------------------------------------------------------------------
__global__ void bn_stats(const float* __restrict__ H, float* stats, int N) {
    int tid = threadIdx.x;
    int col = tid & 63;
    int r = blockIdx.x * 4 + (tid >> 6);
    int rstride = gridDim.x * 4;
    float s = 0.0f, q = 0.0f;
    for (; r < N; r += rstride) {
        float v = H[r * HID + col];
        s += v; q += v * v;
    }
    __shared__ float sh[256], qh[256];
    sh[tid] = s; qh[tid] = q;
    __syncthreads();
    if (tid < 64) {
        float S = sh[tid] + sh[tid + 64] + sh[tid + 128] + sh[tid + 192];
        float Q = qh[tid] + qh[tid + 64] + qh[tid + 128] + qh[tid + 192];
        atomicAdd(&stats[tid], S);
        atomicAdd(&stats[64 + tid], Q);
    }
}

__global__ void bn_relu_dis(const float* __restrict__ H, const float* __restrict__ rawstats,
                            const float* __restrict__ g, const float* __restrict__ beta,
                            const float* __restrict__ dis, __half* __restrict__ out,
                            int total, int N) {
    __shared__ float sc[64], sh[64];
    int t = threadIdx.x;
    if (t < 64) {
        float invN = 1.0f / (float)N;
        float m = rawstats[t] * invN;
        float v = rawstats[64 + t] * invN - m * m;
        float scale = g[t] * rsqrtf(v + BN_EPS);
        sc[t] = scale;
        sh[t] = beta[t] - m * scale;
    }
    __syncthreads();
    int idx = blockIdx.x * blockDim.x + t;
    if (idx >= total) return;
    int f = idx & 63;
    int n = idx >> 6;
    float y = fmaxf(fmaf(H[idx], sc[f], sh[f]), 0.0f);
    out[idx] = __float2half(y * __ldg(&dis[n]));
}

// ---------------------------------------------------------------------------
extern "C" void kernel_launch(void* const* d_in, const int* in_sizes, int n_in,
                              void* d_out, int out_size) {
    const float* x    = (const float*)d_in[0];
    const void*  ei   = d_in[1];
    const float* W1   = (const float*)d_in[2];
    const float* b1   = (const float*)d_in[3];
    const float* g1   = (const float*)d_in[4];
    const float* be1  = (const float*)d_in[5];
    const float* W2   = (const float*)d_in[6];
    const float* b2   = (const float*)d_in[7];
    const float* g2   = (const float*)d_in[8];
    const float* be2  = (const float*)d_in[9];
    const float* Wmu  = (const float*)d_in[10];
    const float* bmu  = (const float*)d_in[11];
    const float* Wls  = (const float*)d_in[12];
    const float* bls  = (const float*)d_in[13];
    float* out = (float*)d_out;

    int N = in_sizes[0] / IND;
    int E = in_sizes[1] / 2;

    float *pA, *pB, *pDis, *pStats;
    __half2* pH;
    int *pCnt, *pRow, *pCur, *pCsr, *pBs;
    cudaGetSymbolAddress((void**)&pA, g_bufA);
    cudaGetSymbolAddress((void**)&pB, g_bufB);
    cudaGetSymbolAddress((void**)&pDis, g_dis);
    cudaGetSymbolAddress((void**)&pStats, g_stats);
    cudaGetSymbolAddress((void**)&pH, g_half);
    cudaGetSymbolAddress((void**)&pCnt, g_cnt);
    cudaGetSymbolAddress((void**)&pRow, g_rowptr);
    cudaGetSymbolAddress((void**)&pCur, g_cursor);
    cudaGetSymbolAddress((void**)&pCsr, g_csr);
    cudaGetSymbolAddress((void**)&pBs, g_bsums);

    float* pStats1 = pStats;
    float* pStats2 = pStats + 128;

    int NH = N * HID;
    int nScanBlocks = (N + SCAN_BLK - 1) / SCAN_BLK;
    int mmaGrid = (N + 63) / 64;
    int aggGrid = ((N + 1) / 2 * 32 + 255) / 256;

    cudaMemsetAsync(pCnt, 0, (size_t)N * sizeof(int));
    cudaMemsetAsync(pStats, 0, 256 * sizeof(float));

    hist_dst<<<(E + 255) / 256, 256>>>(ei, pCnt, E);
    scan1<<<nScanBlocks, SCAN_BLK>>>(pCnt, pRow, pBs, N);
    scan3<<<(N + 255) / 256, 256>>>(pRow, pCur, pBs, pCnt, pDis, N, nScanBlocks);
    scatter_csr<<<(E + 255) / 256, 256>>>(ei, pCur, pCsr, E);

    gemm81_mma<<<mmaGrid, 256>>>(x, W1, pDis, pH, N);
    aggregate_h2<<<aggGrid, 256>>>(pH, pRow, pCsr, pDis, b1, (float4*)pB, N);

    bn_stats<<<512, 256>>>(pB, pStats1, N);

    gemm64_bn_mma<<<mmaGrid, 256>>>(pB, W2, pStats1, g1, be1, pDis, pH, N);
    aggregate_h2<<<aggGrid, 256>>>(pH, pRow, pCsr, pDis, b2, (float4*)pA, N);

    bn_stats<<<512, 256>>>(pA, pStats2, N);

    bn_relu_dis<<<(NH + 255) / 256, 256>>>(pA, pStats2, g2, be2, pDis, (__half*)pH, NH, N);
    aggregate_h2<<<aggGrid, 256>>>(pH, pRow, pCsr, pDis, (const float*)nullptr, (float4*)pB, N);

    gemm_mu_ls_mma<<<mmaGrid, 256>>>(pB, Wmu, bmu, Wls, bls, out, N);
}

// round 17
// speedup vs baseline: 1.2575x; 1.0046x over previous
#include <cuda_runtime.h>
#include <cuda_fp16.h>
#include <cuda_bf16.h>

#define NN 100000
#define EE 3200000
#define IND 81
#define HID 64
#define LAT 32
#define BN_EPS 1e-5f
#define SCAN_BLK 1024
#define XP81 92
#define WP81 92
#define XP64 68

__device__ __align__(128) __half2 g_half[NN * 32];
__device__ float g_bufA[NN * HID];
__device__ float g_bufB[NN * HID];
__device__ float g_dis[NN];
__device__ int   g_cnt[NN];
__device__ int   g_rowptr[NN + 1];
__device__ int   g_cursor[NN + 1];
__device__ int   g_csr[EE];
__device__ int   g_bsums[(NN + SCAN_BLK - 1) / SCAN_BLK + 1];
__device__ float g_stats[256];

// ---------------------------------------------------------------------------
__device__ __forceinline__ bool edges_are_i64(const void* ei) {
    long long v0 = ((const long long*)ei)[0];
    return (v0 >= 0 && v0 < 1000000LL);
}
__device__ __forceinline__ int edge_at(const void* ei, bool is64, int i) {
    return is64 ? (int)((const long long*)ei)[i] : ((const int*)ei)[i];
}
__device__ __forceinline__ unsigned f2tf(float f) {
    unsigned r;
    asm("cvt.rna.tf32.f32 %0, %1;" : "=r"(r) : "f"(f));
    return r;
}
__device__ __forceinline__ void mma_tf32(float* c, unsigned a0, unsigned a1,
                                         unsigned a2, unsigned a3,
                                         unsigned b0, unsigned b1) {
    asm("mma.sync.aligned.m16n8k8.row.col.f32.tf32.tf32.f32 "
        "{%0,%1,%2,%3},{%4,%5,%6,%7},{%8,%9},{%0,%1,%2,%3};"
        : "+f"(c[0]), "+f"(c[1]), "+f"(c[2]), "+f"(c[3])
        : "r"(a0), "r"(a1), "r"(a2), "r"(a3), "r"(b0), "r"(b1));
}

// ---------------------------------------------------------------------------
__global__ void hist_dst(const void* ei, int* cnt, int E) {
    int e = blockIdx.x * blockDim.x + threadIdx.x;
    if (e >= E) return;
    bool is64 = edges_are_i64(ei);
    int d = edge_at(ei, is64, E + e);
    atomicAdd(&cnt[d], 1);
}

// Shfl-based block scan: 3 barriers instead of 20.
__global__ void scan1(const int* __restrict__ cnt, int* __restrict__ rowptr,
                      int* __restrict__ bsums, int n) {
    __shared__ int wsum[32];
    int t = threadIdx.x;
    int lane = t & 31, w = t >> 5;
    int i = blockIdx.x * SCAN_BLK + t;
    int v = (i < n) ? cnt[i] : 0;
    int x = v;
    #pragma unroll
    for (int o = 1; o < 32; o <<= 1) {
        int y = __shfl_up_sync(0xffffffffu, x, o);
        if (lane >= o) x += y;
    }
    if (lane == 31) wsum[w] = x;
    __syncthreads();
    if (w == 0) {
        int s = wsum[lane];
        #pragma unroll
        for (int o = 1; o < 32; o <<= 1) {
            int y = __shfl_up_sync(0xffffffffu, s, o);
            if (lane >= o) s += y;
        }
        wsum[lane] = s;
    }
    __syncthreads();
    int total = x + (w > 0 ? wsum[w - 1] : 0);
    if (i < n) rowptr[i + 1] = total;
    if (t == SCAN_BLK - 1) bsums[blockIdx.x] = total;
}

__global__ void scan3(int* __restrict__ rowptr, int* __restrict__ cursor,
                      const int* __restrict__ bsums, const int* __restrict__ cnt,
                      float* __restrict__ dis, int n, int nb) {
    __shared__ int pre[2];
    int t = threadIdx.x;
    int base = blockIdx.x * 256;
    int jmin = base / SCAN_BLK;
    int jmax = (base + 255) / SCAN_BLK;
    int wid = t >> 5, lane = t & 31;
    if (wid < 2) {
        int j = (wid == 0) ? jmin : jmax;
        int s = 0;
        for (int k = lane; k < j; k += 32) s += bsums[k];
        #pragma unroll
        for (int o = 16; o > 0; o >>= 1) s += __shfl_down_sync(0xffffffffu, s, o);
        if (lane == 0) pre[wid] = s;
    }
    __syncthreads();
    int i = base + t;
    if (i == 0) { rowptr[0] = 0; cursor[0] = 0; }
    if (i < n) {
        int myj = i / SCAN_BLK;
        int off = (myj == jmin) ? pre[0] : pre[1];
        int v = rowptr[i + 1] + off;
        rowptr[i + 1] = v;
        cursor[i + 1] = v;
        dis[i] = rsqrtf((float)(cnt[i] + 1));
    }
}

__global__ void scatter_csr(const void* ei, int* __restrict__ cursor,
                            int* __restrict__ csr, int E) {
    int e = blockIdx.x * blockDim.x + threadIdx.x;
    if (e >= E) return;
    bool is64 = edges_are_i64(ei);
    int s = edge_at(ei, is64, e);
    int d = edge_at(ei, is64, E + e);
    int pos = atomicAdd(&cursor[d], 1);
    csr[pos] = s;
}

// ---------------------------------------------------------------------------
// tf32 tensor-core GEMM: Yh[N,64] = half((X[N,81] @ W[81,64]) * dis[n])
__global__ void gemm81_mma(const float* __restrict__ X, const float* __restrict__ W,
                           const float* __restrict__ dis, __half2* __restrict__ Yh2, int N) {
    __shared__ float Xs[64 * XP81];
    __shared__ float Wt[64 * WP81];
    int tid = threadIdx.x;
    int n0 = blockIdx.x * 64;

    for (int i = tid; i < 64 * XP81; i += 256) Xs[i] = 0.0f;
    for (int i = tid; i < 64 * WP81; i += 256) Wt[i] = 0.0f;
    __syncthreads();
    for (int i = tid; i < 64 * IND; i += 256) {
        int r = i / IND, c = i % IND;
        int n = n0 + r;
        if (n < N) Xs[r * XP81 + c] = X[n * IND + c];
    }
    for (int i = tid; i < IND * HID; i += 256) {
        int k = i >> 6, n = i & 63;
        Wt[n * WP81 + k] = W[i];
    }
    __syncthreads();

    int warp = tid >> 5, lane = tid & 31;
    int mt = warp & 3, nh = warp >> 2;
    int qr = lane >> 2, qc = lane & 3;
    int rowA = mt * 16 + qr;

    float c[4][4];
    #pragma unroll
    for (int t = 0; t < 4; ++t) { c[t][0] = c[t][1] = c[t][2] = c[t][3] = 0.f; }

    for (int k0 = 0; k0 <= 80; k0 += 8) {
        unsigned a0 = f2tf(Xs[rowA * XP81 + k0 + qc]);
        unsigned a1 = f2tf(Xs[(rowA + 8) * XP81 + k0 + qc]);
        unsigned a2 = f2tf(Xs[rowA * XP81 + k0 + 4 + qc]);
        unsigned a3 = f2tf(Xs[(rowA + 8) * XP81 + k0 + 4 + qc]);
        #pragma unroll
        for (int nt = 0; nt < 4; ++nt) {
            int nc = nh * 32 + nt * 8 + qr;
            unsigned b0 = f2tf(Wt[nc * WP81 + k0 + qc]);
            unsigned b1 = f2tf(Wt[nc * WP81 + k0 + 4 + qc]);
            mma_tf32(c[nt], a0, a1, a2, a3, b0, b1);
        }
    }

    int r0 = n0 + mt * 16 + qr;
    int r1 = r0 + 8;
    float d0 = (r0 < N) ? __ldg(&dis[r0]) : 0.f;
    float d1 = (r1 < N) ? __ldg(&dis[r1]) : 0.f;
    #pragma unroll
    for (int nt = 0; nt < 4; ++nt) {
        int cb = nh * 32 + nt * 8 + 2 * qc;
        if (r0 < N) Yh2[r0 * 32 + (cb >> 1)] = __floats2half2_rn(c[nt][0] * d0, c[nt][1] * d0);
        if (r1 < N) Yh2[r1 * 32 + (cb >> 1)] = __floats2half2_rn(c[nt][2] * d1, c[nt][3] * d1);
    }
}

// tf32 GEMM with fused BN-finalize + BN-apply + ReLU; X is fp32 (aggregate output).
__global__ void gemm64_bn_mma(const float* __restrict__ X, const float* __restrict__ W,
                              const float* __restrict__ rawstats,
                              const float* __restrict__ g, const float* __restrict__ beta,
                              const float* __restrict__ dis,
                              __half2* __restrict__ Yh2, int N) {
    __shared__ float Xs[64 * XP64];
    __shared__ float Wt[64 * XP64];
    __shared__ float sc[64], sh[64];
    int tid = threadIdx.x;
    int n0 = blockIdx.x * 64;

    if (tid < 64) {
        float invN = 1.0f / (float)N;
        float m = rawstats[tid] * invN;
        float v = rawstats[64 + tid] * invN - m * m;
        float scale = g[tid] * rsqrtf(v + BN_EPS);
        sc[tid] = scale;
        sh[tid] = beta[tid] - m * scale;
    }
    __syncthreads();
    for (int i = tid; i < 64 * HID; i += 256) {
        int r = i >> 6, cc = i & 63;
        int n = n0 + r;
        float raw = (n < N) ? X[n * HID + cc] : 0.0f;
        Xs[r * XP64 + cc] = fmaxf(fmaf(raw, sc[cc], sh[cc]), 0.0f);
    }
    for (int i = tid; i < HID * HID; i += 256) {
        int k = i >> 6, n = i & 63;
        Wt[n * XP64 + k] = W[i];
    }
    __syncthreads();

    int warp = tid >> 5, lane = tid & 31;
    int mt = warp & 3, nh = warp >> 2;
    int qr = lane >> 2, qc = lane & 3;
    int rowA = mt * 16 + qr;

    float c[4][4];
    #pragma unroll
    for (int t = 0; t < 4; ++t) { c[t][0] = c[t][1] = c[t][2] = c[t][3] = 0.f; }

    for (int k0 = 0; k0 < 64; k0 += 8) {
        unsigned a0 = f2tf(Xs[rowA * XP64 + k0 + qc]);
        unsigned a1 = f2tf(Xs[(rowA + 8) * XP64 + k0 + qc]);
        unsigned a2 = f2tf(Xs[rowA * XP64 + k0 + 4 + qc]);
        unsigned a3 = f2tf(Xs[(rowA + 8) * XP64 + k0 + 4 + qc]);
        #pragma unroll
        for (int nt = 0; nt < 4; ++nt) {
            int nc = nh * 32 + nt * 8 + qr;
            unsigned b0 = f2tf(Wt[nc * XP64 + k0 + qc]);
            unsigned b1 = f2tf(Wt[nc * XP64 + k0 + 4 + qc]);
            mma_tf32(c[nt], a0, a1, a2, a3, b0, b1);
        }
    }

    int r0 = n0 + mt * 16 + qr;
    int r1 = r0 + 8;
    float d0 = (r0 < N) ? __ldg(&dis[r0]) : 0.f;
    float d1 = (r1 < N) ? __ldg(&dis[r1]) : 0.f;
    #pragma unroll
    for (int nt = 0; nt < 4; ++nt) {
        int cb = nh * 32 + nt * 8 + 2 * qc;
        if (r0 < N) Yh2[r0 * 32 + (cb >> 1)] = __floats2half2_rn(c[nt][0] * d0, c[nt][1] * d0);
        if (r1 < N) Yh2[r1 * 32 + (cb >> 1)] = __floats2half2_rn(c[nt][2] * d1, c[nt][3] * d1);
    }
}

// tf32 GEMM for heads: out = [X@Wmu + bmu ; X@Wls + bls], X fp32.
__global__ void gemm_mu_ls_mma(const float* __restrict__ X,
                               const float* __restrict__ Wmu, const float* __restrict__ bmu,
                               const float* __restrict__ Wls, const float* __restrict__ bls,
                               float* __restrict__ out, int N) {
    __shared__ float Xs[64 * XP64];
    __shared__ float Wt[64 * XP64];
    __shared__ float bs[64];
    int tid = threadIdx.x;
    int n0 = blockIdx.x * 64;

    if (tid < 64) bs[tid] = (tid < LAT) ? bmu[tid] : bls[tid - LAT];
    for (int i = tid; i < 64 * HID; i += 256) {
        int r = i >> 6, cc = i & 63;
        int n = n0 + r;
        Xs[r * XP64 + cc] = (n < N) ? X[n * HID + cc] : 0.0f;
    }
    for (int i = tid; i < HID * 64; i += 256) {
        int k = i >> 6, n = i & 63;
        Wt[n * XP64 + k] = (n < LAT) ? Wmu[k * LAT + n] : Wls[k * LAT + (n - LAT)];
    }
    __syncthreads();

    int warp = tid >> 5, lane = tid & 31;
    int mt = warp & 3, nh = warp >> 2;
    int qr = lane >> 2, qc = lane & 3;
    int rowA = mt * 16 + qr;

    float c[4][4];
    #pragma unroll
    for (int t = 0; t < 4; ++t) { c[t][0] = c[t][1] = c[t][2] = c[t][3] = 0.f; }

    for (int k0 = 0; k0 < 64; k0 += 8) {
        unsigned a0 = f2tf(Xs[rowA * XP64 + k0 + qc]);
        unsigned a1 = f2tf(Xs[(rowA + 8) * XP64 + k0 + qc]);
        unsigned a2 = f2tf(Xs[rowA * XP64 + k0 + 4 + qc]);
        unsigned a3 = f2tf(Xs[(rowA + 8) * XP64 + k0 + 4 + qc]);
        #pragma unroll
        for (int nt = 0; nt < 4; ++nt) {
            int nc = nh * 32 + nt * 8 + qr;
            unsigned b0 = f2tf(Wt[nc * XP64 + k0 + qc]);
            unsigned b1 = f2tf(Wt[nc * XP64 + k0 + 4 + qc]);
            mma_tf32(c[nt], a0, a1, a2, a3, b0, b1);
        }
    }

    int r0 = n0 + mt * 16 + qr;
    int r1 = r0 + 8;
    long long headOff = nh ? (long long)N * LAT : 0;
    #pragma unroll
    for (int nt = 0; nt < 4; ++nt) {
        int cb = nh * 32 + nt * 8 + 2 * qc;
        int col = cb & (LAT - 1);
        float bx = bs[cb], by = bs[cb + 1];
        if (r0 < N) {
            float2* p = reinterpret_cast<float2*>(out + headOff + (long long)r0 * LAT + col);
            *p = make_float2(c[nt][0] + bx, c[nt][1] + by);
        }
        if (r1 < N) {
            float2* p = reinterpret_cast<float2*>(out + headOff + (long long)r1 * LAT + col);
            *p = make_float2(c[nt][2] + bx, c[nt][3] + by);
        }
    }
}

// ---------------------------------------------------------------------------
__global__ void aggregate_h2(const __half2* __restrict__ Hh, const int* __restrict__ rowptr,
                             const int* __restrict__ csr, const float* __restrict__ dis,
                             const float* __restrict__ bias, float4* __restrict__ out4, int N) {
    int warp = (blockIdx.x * blockDim.x + threadIdx.x) >> 5;
    int lane = threadIdx.x & 31;
    int grp = lane >> 4;
    int sub = lane & 15;
    int n = warp * 2 + grp;
    if (n >= N) return;

    const uint2* Hr = (const uint2*)Hh;
    uint2 raw = __ldg(&Hr[n * 16 + sub]);
    float2 p0 = __half22float2(*reinterpret_cast<__half2*>(&raw.x));
    float2 p1 = __half22float2(*reinterpret_cast<__half2*>(&raw.y));
    float ax0 = p0.x, ay0 = p0.y, az0 = p1.x, aw0 = p1.y;
    float ax1 = 0.f, ay1 = 0.f, az1 = 0.f, aw1 = 0.f;

    int j = __ldg(&rowptr[n]);
    int end = __ldg(&rowptr[n + 1]);
    for (; j + 2 <= end; j += 2) {
        int s0 = __ldg(&csr[j]);
        int s1 = __ldg(&csr[j + 1]);
        uint2 r0 = __ldg(&Hr[s0 * 16 + sub]);
        uint2 r1 = __ldg(&Hr[s1 * 16 + sub]);
        float2 v00 = __half22float2(*reinterpret_cast<__half2*>(&r0.x));
        float2 v01 = __half22float2(*reinterpret_cast<__half2*>(&r0.y));
        float2 v10 = __half22float2(*reinterpret_cast<__half2*>(&r1.x));
        float2 v11 = __half22float2(*reinterpret_cast<__half2*>(&r1.y));
        ax0 += v00.x; ay0 += v00.y; az0 += v01.x; aw0 += v01.y;
        ax1 += v10.x; ay1 += v10.y; az1 += v11.x; aw1 += v11.y;
    }
    if (j < end) {
        int s0 = __ldg(&csr[j]);
        uint2 r0 = __ldg(&Hr[s0 * 16 + sub]);
        float2 v00 = __half22float2(*reinterpret_cast<__half2*>(&r0.x));
        float2 v01 = __half22float2(*reinterpret_cast<__half2*>(&r0.y));
        ax0 += v00.x; ay0 += v00.y; az0 += v01.x; aw0 += v01.y;
    }

    float dd = __ldg(&dis[n]);
    float4 bb = make_float4(0.f, 0.f, 0.f, 0.f);
    if (bias) bb = ((const float4*)bias)[sub];
    out4[n * 16 + sub] = make_float4(fmaf(ax0 + ax1, dd, bb.x),
                                     fmaf(ay0 + ay1, dd, bb.y),
                                     fmaf(az0 + az1, dd, bb.z),
                                     fmaf(aw0 + aw1, dd, bb.w));
}

// ---------------------------------------------------------------------------
// BN stats, float4 loads: 16 threads per row, 16 rows per block-iteration.
__global__ void bn_stats_v4(const float4* __restrict__ H4, float* stats, int N) {
    int tid = threadIdx.x;            // 256
    int c4 = tid & 15;                // float4 index within row (16 per row)
    int rg = tid >> 4;                // 0..15
    int r = blockIdx.x * 16 + rg;
    int stride = gridDim.x * 16;
    float4 s = make_float4(0.f, 0.f, 0.f, 0.f);
    float4 q = make_float4(0.f, 0.f, 0.f, 0.f);
    for (; r < N; r += stride) {
        float4 v = H4[r * 16 + c4];
        s.x += v.x; s.y += v.y; s.z += v.z; s.w += v.w;
        q.x += v.x * v.x; q.y += v.y * v.y; q.z += v.z * v.z; q.w += v.w * v.w;
    }
    __shared__ float4 sh[256], qh[256];
    sh[tid] = s; qh[tid] = q;
    __syncthreads();
    if (tid < 16) {
        float4 S = sh[tid], Q = qh[tid];
        #pragma unroll
        for (int g = 1; g < 16; ++g) {
            float4 a = sh[g * 16 + tid], b = qh[g * 16 + tid];
            S.x += a.x; S.y += a.y; S.z += a.z; S.w += a.w;
            Q.x += b.x; Q.y += b.y; Q.z += b.z; Q.w += b.w;
        }
        int f = tid * 4;
        atomicAdd(&stats[f + 0], S.x); atomicAdd(&stats[f + 1], S.y);
        atomicAdd(&stats[f + 2], S.z); atomicAdd(&stats[f + 3], S.w);
        atomicAdd(&stats[64 + f + 0], Q.x); atomicAdd(&stats[64 + f + 1], Q.y);
        atomicAdd(&stats[64 + f + 2], Q.z); atomicAdd(&stats[64 + f + 3], Q.w);
    }
}

// Hs = half(relu(bn(B)) * dis), vectorized: 4 feats/thread.
__global__ void bn_relu_dis_v4(const float4* __restrict__ H4, const float* __restrict__ rawstats,
                               const float* __restrict__ g, const float* __restrict__ beta,
                               const float* __restrict__ dis, uint2* __restrict__ out,
                               int total4, int N) {
    __shared__ float sc[64], sh[64];
    int t = threadIdx.x;
    if (t < 64) {
        float invN = 1.0f / (float)N;
        float m = rawstats[t] * invN;
        float v = rawstats[64 + t] * invN - m * m;
        float scale = g[t] * rsqrtf(v + BN_EPS);
        sc[t] = scale;
        sh[t] = beta[t] - m * scale;
    }
    __syncthreads();
    int idx = blockIdx.x * blockDim.x + t;
    if (idx >= total4) return;
    int c4 = idx & 15;
    int n = idx >> 4;
    int f = c4 * 4;
    float dd = __ldg(&dis[n]);
    float4 v = H4[idx];
    float y0 = fmaxf(fmaf(v.x, sc[f], sh[f]), 0.0f) * dd;
    float y1 = fmaxf(fmaf(v.y, sc[f + 1], sh[f + 1]), 0.0f) * dd;
    float y2 = fmaxf(fmaf(v.z, sc[f + 2], sh[f + 2]), 0.0f) * dd;
    float y3 = fmaxf(fmaf(v.w, sc[f + 3], sh[f + 3]), 0.0f) * dd;
    uint2 o;
    __half2 h0 = __floats2half2_rn(y0, y1);
    __half2 h1 = __floats2half2_rn(y2, y3);
    o.x = *reinterpret_cast<unsigned*>(&h0);
    o.y = *reinterpret_cast<unsigned*>(&h1);
    out[idx] = o;
}

// ---------------------------------------------------------------------------
extern "C" void kernel_launch(void* const* d_in, const int* in_sizes, int n_in,
                              void* d_out, int out_size) {
    const float* x    = (const float*)d_in[0];
    const void*  ei   = d_in[1];
    const float* W1   = (const float*)d_in[2];
    const float* b1   = (const float*)d_in[3];
    const float* g1   = (const float*)d_in[4];
    const float* be1  = (const float*)d_in[5];
    const float* W2   = (const float*)d_in[6];
    const float* b2   = (const float*)d_in[7];
    const float* g2   = (const float*)d_in[8];
    const float* be2  = (const float*)d_in[9];
    const float* Wmu  = (const float*)d_in[10];
    const float* bmu  = (const float*)d_in[11];
    const float* Wls  = (const float*)d_in[12];
    const float* bls  = (const float*)d_in[13];
    float* out = (float*)d_out;

    int N = in_sizes[0] / IND;
    int E = in_sizes[1] / 2;

    float *pA, *pB, *pDis, *pStats;
    __half2* pH;
    int *pCnt, *pRow, *pCur, *pCsr, *pBs;
    cudaGetSymbolAddress((void**)&pA, g_bufA);
    cudaGetSymbolAddress((void**)&pB, g_bufB);
    cudaGetSymbolAddress((void**)&pDis, g_dis);
    cudaGetSymbolAddress((void**)&pStats, g_stats);
    cudaGetSymbolAddress((void**)&pH, g_half);
    cudaGetSymbolAddress((void**)&pCnt, g_cnt);
    cudaGetSymbolAddress((void**)&pRow, g_rowptr);
    cudaGetSymbolAddress((void**)&pCur, g_cursor);
    cudaGetSymbolAddress((void**)&pCsr, g_csr);
    cudaGetSymbolAddress((void**)&pBs, g_bsums);

    float* pStats1 = pStats;
    float* pStats2 = pStats + 128;

    int nScanBlocks = (N + SCAN_BLK - 1) / SCAN_BLK;
    int mmaGrid = (N + 63) / 64;
    int aggGrid = ((N + 1) / 2 * 32 + 255) / 256;
    int total4 = N * 16;

    cudaMemsetAsync(pCnt, 0, (size_t)N * sizeof(int));
    cudaMemsetAsync(pStats, 0, 256 * sizeof(float));

    hist_dst<<<(E + 255) / 256, 256>>>(ei, pCnt, E);
    scan1<<<nScanBlocks, SCAN_BLK>>>(pCnt, pRow, pBs, N);
    scan3<<<(N + 255) / 256, 256>>>(pRow, pCur, pBs, pCnt, pDis, N, nScanBlocks);
    scatter_csr<<<(E + 255) / 256, 256>>>(ei, pCur, pCsr, E);

    gemm81_mma<<<mmaGrid, 256>>>(x, W1, pDis, pH, N);
    aggregate_h2<<<aggGrid, 256>>>(pH, pRow, pCsr, pDis, b1, (float4*)pB, N);

    bn_stats_v4<<<512, 256>>>((const float4*)pB, pStats1, N);

    gemm64_bn_mma<<<mmaGrid, 256>>>(pB, W2, pStats1, g1, be1, pDis, pH, N);
    aggregate_h2<<<aggGrid, 256>>>(pH, pRow, pCsr, pDis, b2, (float4*)pA, N);

    bn_stats_v4<<<512, 256>>>((const float4*)pA, pStats2, N);

    bn_relu_dis_v4<<<(total4 + 255) / 256, 256>>>((const float4*)pA, pStats2, g2, be2,
                                                  pDis, (uint2*)pH, total4, N);
    aggregate_h2<<<aggGrid, 256>>>(pH, pRow, pCsr, pDis, (const float*)nullptr, (float4*)pB, N);

    gemm_mu_ls_mma<<<mmaGrid, 256>>>(pB, Wmu, bmu, Wls, bls, out, N);
}